// round 10
// baseline (speedup 1.0000x reference)
#include <cuda_runtime.h>
#include <cuda_fp16.h>
#include <math.h>
#include <cstdint>

// Problem constants
#define BDIM 4096
#define HDIM 1024
#define SDIM 256
#define NSAMP 256
#define TSTEPS 10
#define RHDIM 512
#define N3 3072

// k1/k3 tiling: BM=256, BN=32, 16 warps x (16 rows x 32 cols), 512 threads
#define BM1 256
#define AROW 20              // A smem row stride in words (32 halves + pad 8)
#define ASTG1 5120           // A words per stage (256*20)
#define ABASE1 15360         // 3 * ASTG1
// k2 tiling: BM=128, 8 warps, 256 threads (unchanged)
#define BM 128
#define BN 32
#define ASTG 2560
#define ABASE 7680
#define BROW 40              // B smem k2-row stride in words
#define NB1 1920
#define NB2 1280
#define NB3 640

// Persistent scratch
__device__ float g_h[2][BDIM * HDIM];
__device__ __half g_h16[2][BDIM * HDIM];
__device__ __half g_s16[BDIM * SDIM];
__device__ float g_acc[BDIM];
// per-step per-CTA-column partial sums (deterministic, no atomics)
__device__ float g_hS[TSTEPS * 32 * BDIM];
__device__ float g_hQ[TSTEPS * 32 * BDIM];
__device__ float g_sS[TSTEPS * 8 * BDIM];
__device__ float g_sQ[TSTEPS * 8 * BDIM];
__device__ float g_rD[TSTEPS * 16 * BDIM];
// Pre-packed half2 weights
__device__ uint32_t W1h[32 * 40 * 3 * 16 * 32];
__device__ uint32_t W2h[8 * 32 * 2 * 16 * 32];
__device__ uint32_t W3h[16 * 40 * 16 * 32];

__device__ __forceinline__ float sigm_(float x) { return 1.0f / (1.0f + expf(-x)); }
__device__ __forceinline__ float softplus_(float x) {
    return fmaxf(x, 0.0f) + log1pf(expf(-fabsf(x)));
}
__device__ __forceinline__ uint32_t pack2(float lo, float hi) {
    __half2 h = __floats2half2_rn(lo, hi);
    return *(uint32_t*)&h;
}
__device__ __forceinline__ float red4(float v) {
    v += __shfl_xor_sync(0xffffffffu, v, 1);
    v += __shfl_xor_sync(0xffffffffu, v, 2);
    return v;
}
__device__ __forceinline__ void mma_f16(float c[4], uint32_t a0, uint32_t a1,
                                        uint32_t a2, uint32_t a3,
                                        uint32_t b0, uint32_t b1) {
    asm volatile(
        "mma.sync.aligned.m16n8k16.row.col.f32.f16.f16.f32 "
        "{%0,%1,%2,%3},{%4,%5,%6,%7},{%8,%9},{%0,%1,%2,%3};\n"
        : "+f"(c[0]), "+f"(c[1]), "+f"(c[2]), "+f"(c[3])
        : "r"(a0), "r"(a1), "r"(a2), "r"(a3), "r"(b0), "r"(b1));
}
__device__ __forceinline__ void ldsm4(uint32_t& r0, uint32_t& r1, uint32_t& r2,
                                      uint32_t& r3, uint32_t addr) {
    asm volatile("ldmatrix.sync.aligned.m8n8.x4.shared.b16 {%0,%1,%2,%3}, [%4];"
                 : "=r"(r0), "=r"(r1), "=r"(r2), "=r"(r3) : "r"(addr));
}
__device__ __forceinline__ void cp16(uint32_t dst, const void* src) {
    asm volatile("cp.async.cg.shared.global [%0], [%1], 16;" :: "r"(dst), "l"(src));
}
__device__ __forceinline__ void cp_commit() { asm volatile("cp.async.commit_group;"); }
template<int N> __device__ __forceinline__ void cp_wait() {
    asm volatile("cp.async.wait_group %0;" :: "n"(N));
}

// ---------------------------------------------------------------------------
// init + weight packing
// ---------------------------------------------------------------------------
__global__ void k_init(const float* __restrict__ h0, const float* __restrict__ s0) {
    int idx = blockIdx.x * blockDim.x + threadIdx.x;
    int stride = gridDim.x * blockDim.x;
    for (int i = idx; i < BDIM * HDIM; i += stride) {
        float v = h0[i & (HDIM - 1)];
        g_h[0][i] = v; g_h16[0][i] = __float2half_rn(v);
    }
    for (int i = idx; i < BDIM * SDIM; i += stride)
        g_s16[i] = __float2half_rn(s0[i & (SDIM - 1)]);
}

__global__ void k_prep1(const float* __restrict__ Wx, const float* __restrict__ Wh) {
    const int total = 32 * 40 * 3 * 16 * 32;
    for (int idx = blockIdx.x * blockDim.x + threadIdx.x; idx < total;
         idx += gridDim.x * blockDim.x) {
        int p = idx & 31, k2 = (idx >> 5) & 15;
        int rest = idx >> 9;
        int g = rest % 3; rest /= 3;
        int kt = rest % 40; int cb = rest / 40;
        int c = (p & 3) * 8 + (p >> 2);
        int col = g * HDIM + cb * 32 + c;
        int row = kt * 32 + 2 * k2;
        float vlo, vhi;
        if (row < 256) { vlo = Wx[(size_t)row * N3 + col]; vhi = Wx[(size_t)(row + 1) * N3 + col]; }
        else { vlo = Wh[(size_t)(row - 256) * N3 + col]; vhi = Wh[(size_t)(row - 255) * N3 + col]; }
        W1h[idx] = pack2(vlo, vhi);
    }
}
__global__ void k_prep2(const float* __restrict__ W_mu, const float* __restrict__ W_std) {
    const int total = 8 * 32 * 2 * 16 * 32;
    for (int idx = blockIdx.x * blockDim.x + threadIdx.x; idx < total;
         idx += gridDim.x * blockDim.x) {
        int p = idx & 31, k2 = (idx >> 5) & 15;
        int rest = idx >> 9;
        int g = rest & 1; rest >>= 1;
        int kt = rest & 31; int cb = rest >> 5;
        int c = (p & 3) * 8 + (p >> 2);
        const float* W = g ? W_std : W_mu;
        int row = kt * 32 + 2 * k2;
        W2h[idx] = pack2(W[(size_t)row * SDIM + cb * 32 + c],
                         W[(size_t)(row + 1) * SDIM + cb * 32 + c]);
    }
}
__global__ void k_prep3(const float* __restrict__ W_r1) {
    const int total = 16 * 40 * 16 * 32;
    for (int idx = blockIdx.x * blockDim.x + threadIdx.x; idx < total;
         idx += gridDim.x * blockDim.x) {
        int p = idx & 31, k2 = (idx >> 5) & 15;
        int rest = idx >> 9;
        int kt = rest % 40; int cb = rest / 40;
        int c = (p & 3) * 8 + (p >> 2);
        int row = kt * 32 + 2 * k2;
        W3h[idx] = pack2(W_r1[(size_t)row * RHDIM + cb * 32 + c],
                         W_r1[(size_t)(row + 1) * RHDIM + cb * 32 + c]);
    }
}

// ---------------------------------------------------------------------------
// K1 tile body (512 threads, BM=256): GRU gates GEMM + h update + partials.
// ---------------------------------------------------------------------------
__device__ __forceinline__
void k1_body(int par, int t, const float* __restrict__ Wx,
             const float* __restrict__ b_gru, const int* __restrict__ acts_t, int by) {
    extern __shared__ uint32_t smem[];
    const float* __restrict__ h_in = g_h[par];
    float* __restrict__ h_out = g_h[par ^ 1];
    const __half* __restrict__ h16_in = g_h16[par];
    __half* __restrict__ h16_out = g_h16[par ^ 1];

    const int tid = threadIdx.x, lane = tid & 31, warp = tid >> 5;
    const int row0 = blockIdx.x * BM1, col0 = by * BN;
    const int wr = warp * 16;
    const uint32_t smem_b = (uint32_t)__cvta_generic_to_shared(smem);

    // A: 2 chunks/thread (rows rA, rA+128)
    const int c4 = tid & 3, rA = tid >> 2;
    const int wA0 = rA * AROW + c4 * 4, wA1 = (rA + 128) * AROW + c4 * 4;
    const __half* sA = g_s16 + (size_t)(row0 + rA) * SDIM + c4 * 8;
    const __half* hA = h16_in + (size_t)(row0 + rA) * HDIM + c4 * 8;
    // B: one chunk for tid<384
    const int bg0 = tid >> 7, bk0 = (tid >> 3) & 15, bc0 = tid & 7;
    const int wB0 = bg0 * 640 + bk0 * BROW + bc0 * 4;
    const int sB0w = bg0 * 512 + bk0 * 32 + bc0 * 4;
    const uint32_t* wblk = W1h + (size_t)by * (40 * 3 * 512);

#define K1_ISSUE(kt, s) do {                                                  \
    const __half* ap; int astr;                                               \
    if ((kt) < 8) { ap = sA + (kt) * 32; astr = SDIM; }                       \
    else { ap = hA + ((kt) - 8) * 32; astr = HDIM; }                          \
    cp16(smem_b + 4 * ((s) * ASTG1 + wA0), ap);                               \
    cp16(smem_b + 4 * ((s) * ASTG1 + wA1), ap + 128 * astr);                  \
    if (tid < 384)                                                            \
        cp16(smem_b + 4 * (ABASE1 + (s) * NB1 + wB0),                         \
             wblk + (size_t)(kt) * 1536 + sB0w);                              \
    cp_commit(); } while (0)

    float acc[3][4][4], accNX[4][4];
#pragma unroll
    for (int g = 0; g < 3; g++)
#pragma unroll
        for (int nt = 0; nt < 4; nt++)
#pragma unroll
            for (int r = 0; r < 4; r++) acc[g][nt][r] = 0.0f;

    const int q = lane >> 2, klo = lane & 3;
    const int r1 = wr + q;
    const int bfr = klo * BROW + q * 4;
    const uint32_t aBase = smem_b + (uint32_t)(wr + (lane & 15)) * AROW * 4
                         + ((lane >> 4) * 16);

    K1_ISSUE(0, 0);
    K1_ISSUE(1, 1);

    const int KT = 40;
#pragma unroll 1
    for (int kt = 0; kt < KT; ++kt) {
        if (kt + 1 < KT) cp_wait<1>(); else cp_wait<0>();
        __syncthreads();
        if (kt + 2 < KT) K1_ISSUE(kt + 2, (kt + 2) % 3);

        if (kt == 8) {
#pragma unroll
            for (int nt = 0; nt < 4; nt++)
#pragma unroll
                for (int r = 0; r < 4; r++) { accNX[nt][r] = acc[2][nt][r]; acc[2][nt][r] = 0.0f; }
        }
        const int sA_ = (kt % 3) * ASTG1;
        const int sB_ = ABASE1 + (kt % 3) * NB1;
#pragma unroll
        for (int kc = 0; kc < 2; ++kc) {
            uint32_t a0, a1, a2, a3;
            ldsm4(a0, a1, a2, a3, aBase + 4 * sA_ + kc * 32);
#pragma unroll
            for (int g = 0; g < 3; g++) {
                const int bb = sB_ + g * 640 + 8 * kc * BROW + bfr;
                uint4 b0 = *(const uint4*)&smem[bb];
                uint4 b1 = *(const uint4*)&smem[bb + 4 * BROW];
                mma_f16(acc[g][0], a0, a1, a2, a3, b0.x, b1.x);
                mma_f16(acc[g][1], a0, a1, a2, a3, b0.y, b1.y);
                mma_f16(acc[g][2], a0, a1, a2, a3, b0.z, b1.z);
                mma_f16(acc[g][3], a0, a1, a2, a3, b0.w, b1.w);
            }
        }
    }
#undef K1_ISSUE

    float sumr[2] = {0.0f, 0.0f}, sqr[2] = {0.0f, 0.0f};
#pragma unroll
    for (int ri = 0; ri < 2; ri++) {
        int b = row0 + r1 + ri * 8;
        int a = acts_t[b];
        const float* wa = Wx + (size_t)(SDIM + a) * N3;
#pragma unroll
        for (int nt = 0; nt < 4; nt++) {
#pragma unroll
            for (int cj = 0; cj < 2; cj++) {
                int c = col0 + nt * 8 + 2 * klo + cj;
                int idx = ri * 2 + cj;
                float z = sigm_(acc[0][nt][idx] + wa[c] + b_gru[c]);
                float r = sigm_(acc[1][nt][idx] + wa[HDIM + c] + b_gru[HDIM + c]);
                float n = tanhf(accNX[nt][idx] + wa[2 * HDIM + c]
                                + r * acc[2][nt][idx] + b_gru[2 * HDIM + c]);
                float hp = h_in[(size_t)b * HDIM + c];
                float hv = (1.0f - z) * hp + z * n;
                h_out[(size_t)b * HDIM + c] = hv;
                h16_out[(size_t)b * HDIM + c] = __float2half_rn(hv);
                sumr[ri] += hv;
                sqr[ri] = fmaf(hv, hv, sqr[ri]);
            }
        }
    }
#pragma unroll
    for (int ri = 0; ri < 2; ri++) {
        float S = red4(sumr[ri]);
        float Q = red4(sqr[ri]);
        if (klo == 0) {
            int b = row0 + r1 + ri * 8;
            g_hS[(size_t)(t * 32 + by) * BDIM + b] = S;
            g_hQ[(size_t)(t * 32 + by) * BDIM + b] = Q;
        }
    }
}

// ---------------------------------------------------------------------------
// K3 tile body (512 threads, BM=256): reward GEMM + fused relu.w_r2 dot.
// ---------------------------------------------------------------------------
__device__ __forceinline__
void k3_body(int parn, int t, const float* __restrict__ b_r1,
             const float* __restrict__ w_r2, int by) {
    extern __shared__ uint32_t smem[];
    const __half* __restrict__ h16 = g_h16[parn];

    const int tid = threadIdx.x, lane = tid & 31, warp = tid >> 5;
    const int row0 = blockIdx.x * BM1, col0 = by * BN;
    const int wr = warp * 16;
    const uint32_t smem_b = (uint32_t)__cvta_generic_to_shared(smem);

    const int c4 = tid & 3, rA = tid >> 2;
    const int wA0 = rA * AROW + c4 * 4, wA1 = (rA + 128) * AROW + c4 * 4;
    const __half* hA = h16 + (size_t)(row0 + rA) * HDIM + c4 * 8;
    const __half* sA = g_s16 + (size_t)(row0 + rA) * SDIM + c4 * 8;
    const int wB0 = (tid >> 3) * BROW + (tid & 7) * 4;   // tid<128 only
    const int sB0w = (tid >> 3) * 32 + (tid & 7) * 4;
    const uint32_t* wblk = W3h + (size_t)by * (40 * 512);

#define K3_ISSUE(kt, s) do {                                                  \
    const __half* ap; int astr;                                               \
    if ((kt) < 32) { ap = hA + (kt) * 32; astr = HDIM; }                      \
    else { ap = sA + ((kt) - 32) * 32; astr = SDIM; }                         \
    cp16(smem_b + 4 * ((s) * ASTG1 + wA0), ap);                               \
    cp16(smem_b + 4 * ((s) * ASTG1 + wA1), ap + 128 * astr);                  \
    if (tid < 128)                                                            \
        cp16(smem_b + 4 * (ABASE1 + (s) * NB3 + wB0),                         \
             wblk + (size_t)(kt) * 512 + sB0w);                               \
    cp_commit(); } while (0)

    float acc[4][4];
#pragma unroll
    for (int nt = 0; nt < 4; nt++)
#pragma unroll
        for (int r = 0; r < 4; r++) acc[nt][r] = 0.0f;

    const int q = lane >> 2, klo = lane & 3;
    const int r1 = wr + q;
    const int bfr = klo * BROW + q * 4;
    const uint32_t aBase = smem_b + (uint32_t)(wr + (lane & 15)) * AROW * 4
                         + ((lane >> 4) * 16);

    K3_ISSUE(0, 0);
    K3_ISSUE(1, 1);

    const int KT = 40;
#pragma unroll 1
    for (int kt = 0; kt < KT; ++kt) {
        if (kt + 1 < KT) cp_wait<1>(); else cp_wait<0>();
        __syncthreads();
        if (kt + 2 < KT) K3_ISSUE(kt + 2, (kt + 2) % 3);

        const int sA_ = (kt % 3) * ASTG1;
        const int sB_ = ABASE1 + (kt % 3) * NB3;
#pragma unroll
        for (int kc = 0; kc < 2; ++kc) {
            uint32_t a0, a1, a2, a3;
            ldsm4(a0, a1, a2, a3, aBase + 4 * sA_ + kc * 32);
            const int bb = sB_ + 8 * kc * BROW + bfr;
            uint4 b0 = *(const uint4*)&smem[bb];
            uint4 b1 = *(const uint4*)&smem[bb + 4 * BROW];
            mma_f16(acc[0], a0, a1, a2, a3, b0.x, b1.x);
            mma_f16(acc[1], a0, a1, a2, a3, b0.y, b1.y);
            mma_f16(acc[2], a0, a1, a2, a3, b0.z, b1.z);
            mma_f16(acc[3], a0, a1, a2, a3, b0.w, b1.w);
        }
    }
#undef K3_ISSUE

    float dotr[2] = {0.0f, 0.0f};
#pragma unroll
    for (int ri = 0; ri < 2; ri++) {
#pragma unroll
        for (int nt = 0; nt < 4; nt++) {
#pragma unroll
            for (int cj = 0; cj < 2; cj++) {
                int c = col0 + nt * 8 + 2 * klo + cj;
                int idx = ri * 2 + cj;
                float rv = fmaxf(acc[nt][idx] + b_r1[c], 0.0f);
                dotr[ri] = fmaf(rv, w_r2[c], dotr[ri]);
            }
        }
    }
#pragma unroll
    for (int ri = 0; ri < 2; ri++) {
        float D = red4(dotr[ri]);
        if (klo == 0) {
            int b = row0 + r1 + ri * 8;
            g_rD[(size_t)(t * 16 + by) * BDIM + b] = D;
        }
    }
}

// ---------------------------------------------------------------------------
// Merged k1(t) + k3(t-1): identical inputs, disjoint outputs.
// grid (16, 48) for t>=1; (16, 32) for t=0. 512 threads.
// ---------------------------------------------------------------------------
__global__ __launch_bounds__(512, 1)
void k13(int par, int t, const float* __restrict__ Wx, const float* __restrict__ b_gru,
         const int* __restrict__ acts_t, const float* __restrict__ b_r1,
         const float* __restrict__ w_r2) {
    if (blockIdx.y < 32) k1_body(par, t, Wx, b_gru, acts_t, blockIdx.y);
    else k3_body(par, t - 1, b_r1, w_r2, blockIdx.y - 32);
}

__global__ __launch_bounds__(512, 1)
void k3k(int parn, int t, const float* __restrict__ b_r1, const float* __restrict__ w_r2) {
    k3_body(parn, t, b_r1, w_r2, blockIdx.y);
}

// ---------------------------------------------------------------------------
// K2: mu/std GEMM + latent sample + s partial sums. grid (32,8), 256 thr.
// ---------------------------------------------------------------------------
__global__ __launch_bounds__(256, 2)
void k2_latent(int parn, int t, const float* __restrict__ b_mu,
               const float* __restrict__ b_std, const float* __restrict__ noise_t) {
    extern __shared__ uint32_t smem[];
    const __half* __restrict__ h16 = g_h16[parn];

    const int tid = threadIdx.x, lane = tid & 31, warp = tid >> 5;
    const int row0 = blockIdx.x * BM, col0 = blockIdx.y * BN, by = blockIdx.y;
    const int wr = warp * 16;
    const uint32_t smem_b = (uint32_t)__cvta_generic_to_shared(smem);

    const int c4 = tid & 3, rA = tid >> 2;
    const int wA0 = rA * AROW + c4 * 4, wA1 = (rA + 64) * AROW + c4 * 4;
    const __half* hA = h16 + (size_t)(row0 + rA) * HDIM + c4 * 8;
    const int bg0 = tid >> 7, bk0 = (tid >> 3) & 15, bc0 = tid & 7;
    const int wB0 = bg0 * 640 + bk0 * BROW + bc0 * 4;
    const int sB0w = bg0 * 512 + bk0 * 32 + bc0 * 4;
    const uint32_t* wblk = W2h + (size_t)blockIdx.y * (32 * 2 * 512);

#define K2_ISSUE(kt, s) do {                                                  \
    const __half* ap = hA + (kt) * 32;                                        \
    cp16(smem_b + 4 * ((s) * ASTG + wA0), ap);                                \
    cp16(smem_b + 4 * ((s) * ASTG + wA1), ap + 64 * HDIM);                    \
    const uint32_t* wp = wblk + (size_t)(kt) * 1024;                          \
    cp16(smem_b + 4 * (ABASE + (s) * NB2 + wB0), wp + sB0w);                  \
    cp_commit(); } while (0)

    float acc[2][4][4];
#pragma unroll
    for (int g = 0; g < 2; g++)
#pragma unroll
        for (int nt = 0; nt < 4; nt++)
#pragma unroll
            for (int r = 0; r < 4; r++) acc[g][nt][r] = 0.0f;

    const int q = lane >> 2, klo = lane & 3;
    const int r1 = wr + q;
    const int bfr = klo * BROW + q * 4;
    const uint32_t aBase = smem_b + (uint32_t)(wr + (lane & 15)) * AROW * 4
                         + ((lane >> 4) * 16);

    K2_ISSUE(0, 0);
    K2_ISSUE(1, 1);

    const int KT = 32;
#pragma unroll 1
    for (int kt = 0; kt < KT; ++kt) {
        if (kt + 1 < KT) cp_wait<1>(); else cp_wait<0>();
        __syncthreads();
        if (kt + 2 < KT) K2_ISSUE(kt + 2, (kt + 2) % 3);

        const int sA_ = (kt % 3) * ASTG;
        const int sB_ = ABASE + (kt % 3) * NB2;
#pragma unroll
        for (int kc = 0; kc < 2; ++kc) {
            uint32_t a0, a1, a2, a3;
            ldsm4(a0, a1, a2, a3, aBase + 4 * sA_ + kc * 32);
#pragma unroll
            for (int g = 0; g < 2; g++) {
                const int bb = sB_ + g * 640 + 8 * kc * BROW + bfr;
                uint4 b0 = *(const uint4*)&smem[bb];
                uint4 b1 = *(const uint4*)&smem[bb + 4 * BROW];
                mma_f16(acc[g][0], a0, a1, a2, a3, b0.x, b1.x);
                mma_f16(acc[g][1], a0, a1, a2, a3, b0.y, b1.y);
                mma_f16(acc[g][2], a0, a1, a2, a3, b0.z, b1.z);
                mma_f16(acc[g][3], a0, a1, a2, a3, b0.w, b1.w);
            }
        }
    }
#undef K2_ISSUE

    float sumr[2] = {0.0f, 0.0f}, sqr[2] = {0.0f, 0.0f};
#pragma unroll
    for (int ri = 0; ri < 2; ri++) {
        int b = row0 + r1 + ri * 8;
#pragma unroll
        for (int nt = 0; nt < 4; nt++) {
#pragma unroll
            for (int cj = 0; cj < 2; cj++) {
                int c = col0 + nt * 8 + 2 * klo + cj;
                int idx = ri * 2 + cj;
                float mu = acc[0][nt][idx] + b_mu[c];
                float sd = softplus_(acc[1][nt][idx] + b_std[c]) + 0.1f;
                float sv = mu + sd * noise_t[(size_t)b * SDIM + c];
                g_s16[(size_t)b * SDIM + c] = __float2half_rn(sv);
                sumr[ri] += sv;
                sqr[ri] = fmaf(sv, sv, sqr[ri]);
            }
        }
    }
#pragma unroll
    for (int ri = 0; ri < 2; ri++) {
        float S = red4(sumr[ri]);
        float Q = red4(sqr[ri]);
        if (klo == 0) {
            int b = row0 + r1 + ri * 8;
            g_sS[(size_t)(t * 8 + by) * BDIM + b] = S;
            g_sQ[(size_t)(t * 8 + by) * BDIM + b] = Q;
        }
    }
}

// ---------------------------------------------------------------------------
// k_efe: fold all per-step partials into g_acc (once). grid 16 x 256.
// ---------------------------------------------------------------------------
__global__ void k_efe() {
    const int b = blockIdx.x * 256 + threadIdx.x;
    float acc = 0.0f, disc = 1.0f;
#pragma unroll 1
    for (int t = 0; t < TSTEPS; t++) {
        float S = 0.0f, Q = 0.0f, D = 0.0f;
#pragma unroll
        for (int i = 0; i < 32; i++) {
            S += g_hS[(size_t)(t * 32 + i) * BDIM + b];
            Q += g_hQ[(size_t)(t * 32 + i) * BDIM + b];
        }
#pragma unroll
        for (int i = 0; i < 8; i++) {
            S += g_sS[(size_t)(t * 8 + i) * BDIM + b];
            Q += g_sQ[(size_t)(t * 8 + i) * BDIM + b];
        }
#pragma unroll
        for (int i = 0; i < 16; i++) D += g_rD[(size_t)(t * 16 + i) * BDIM + b];
        float mean = S * (1.0f / 1280.0f);
        float var = Q * (1.0f / 1280.0f) - mean * mean;
        acc += disc * (D + var);
        disc *= 0.99f;
    }
    g_acc[b] = acc;
}

__global__ void k_final(float* __restrict__ out, const float* __restrict__ b_r2,
                        float discsum) {
    const int a = blockIdx.x;
    const int tid = threadIdx.x;
    float v = g_acc[a * NSAMP + tid];
#pragma unroll
    for (int off = 16; off > 0; off >>= 1) v += __shfl_down_sync(0xffffffffu, v, off);
    __shared__ float w[8];
    if ((tid & 31) == 0) w[tid >> 5] = v;
    __syncthreads();
    if (tid < 8) {
        float x = w[tid];
#pragma unroll
        for (int off = 4; off > 0; off >>= 1) x += __shfl_down_sync(0xffu, x, off);
        if (tid == 0) out[a] = -(x * (1.0f / (float)NSAMP) + discsum * b_r2[0]);
    }
}

// ---------------------------------------------------------------------------
extern "C" void kernel_launch(void* const* d_in, const int* in_sizes, int n_in,
                              void* d_out, int out_size) {
    (void)in_sizes; (void)n_in; (void)out_size;
    const float* h0    = (const float*)d_in[0];
    const float* s0    = (const float*)d_in[1];
    const float* noise = (const float*)d_in[2];
    const float* Wx    = (const float*)d_in[3];
    const float* Wh    = (const float*)d_in[4];
    const float* b_gru = (const float*)d_in[5];
    const float* W_mu  = (const float*)d_in[6];
    const float* b_mu  = (const float*)d_in[7];
    const float* W_std = (const float*)d_in[8];
    const float* b_std = (const float*)d_in[9];
    const float* W_r1  = (const float*)d_in[10];
    const float* b_r1  = (const float*)d_in[11];
    const float* w_r2  = (const float*)d_in[12];
    const float* b_r2  = (const float*)d_in[13];
    const int*   acts  = (const int*)d_in[14];
    float* out = (float*)d_out;

    const int SM1 = (ABASE1 + 3 * NB1) * 4;  // 84480 B
    const int SM2 = (ABASE + 3 * NB2) * 4;   // 46080 B
    cudaFuncSetAttribute(k13, cudaFuncAttributeMaxDynamicSharedMemorySize, SM1);
    cudaFuncSetAttribute(k3k, cudaFuncAttributeMaxDynamicSharedMemorySize, SM1);
    cudaFuncSetAttribute(k2_latent, cudaFuncAttributeMaxDynamicSharedMemorySize, SM2);

    k_init<<<512, 256>>>(h0, s0);
    k_prep1<<<2048, 256>>>(Wx, Wh);
    k_prep2<<<256, 256>>>(W_mu, W_std);
    k_prep3<<<320, 256>>>(W_r1);

    for (int t = 0; t < TSTEPS; ++t) {
        int par = t & 1;
        int parn = par ^ 1;
        int ny = (t == 0) ? 32 : 48;
        k13<<<dim3(BDIM / BM1, ny), 512, SM1>>>(par, t, Wx, b_gru,
                                                acts + (size_t)t * BDIM, b_r1, w_r2);
        k2_latent<<<dim3(BDIM / BM, SDIM / BN), 256, SM2>>>(parn, t, b_mu, b_std,
                                                            noise + (size_t)t * BDIM * SDIM);
    }
    // final step's reward GEMM (state after t=9: parn = (9&1)^1 = 0)
    k3k<<<dim3(BDIM / BM1, RHDIM / BN), 512, SM1>>>(0, TSTEPS - 1, b_r1, w_r2);
    k_efe<<<16, 256>>>();

    float discsum = 0.0f, d = 1.0f;
    for (int t = 0; t < TSTEPS; ++t) { discsum += d; d *= 0.99f; }
    k_final<<<16, 256>>>(out, b_r2, discsum);
}

// round 11
// speedup vs baseline: 1.1651x; 1.1651x over previous
#include <cuda_runtime.h>
#include <cuda_fp16.h>
#include <math.h>
#include <cstdint>

// Problem constants
#define BDIM 4096
#define HDIM 1024
#define SDIM 256
#define NSAMP 256
#define TSTEPS 10
#define RHDIM 512
#define N3 3072

// Tiling: BM=128, BN=32, BK=32 (halves), 8 warps x (16 rows x 32 cols)
#define BM 128
#define BN 32
#define AROW 20              // A smem row stride in words (32 halves + pad 8)
#define ASTG 2560            // A words per stage (128*20)
#define NSTG 4               // pipeline stages
#define ABASE 10240          // NSTG * ASTG
#define BROW 40              // B smem k2-row stride in words
#define NB1 1920
#define NB2 1280
#define NB3 640

// Persistent scratch
__device__ float g_h[2][BDIM * HDIM];
__device__ __half g_h16[2][BDIM * HDIM];
__device__ __half g_s16[BDIM * SDIM];
__device__ float g_acc[BDIM];
// per-step per-CTA-column partial sums (deterministic, no atomics)
__device__ float g_hS[TSTEPS * 32 * BDIM];
__device__ float g_hQ[TSTEPS * 32 * BDIM];
__device__ float g_sS[TSTEPS * 8 * BDIM];
__device__ float g_sQ[TSTEPS * 8 * BDIM];
__device__ float g_rD[TSTEPS * 16 * BDIM];
// Pre-packed half2 weights
__device__ uint32_t W1h[32 * 40 * 3 * 16 * 32];
__device__ uint32_t W2h[8 * 32 * 2 * 16 * 32];
__device__ uint32_t W3h[16 * 40 * 16 * 32];

__device__ __forceinline__ float sigm_(float x) { return 1.0f / (1.0f + expf(-x)); }
__device__ __forceinline__ float softplus_(float x) {
    return fmaxf(x, 0.0f) + log1pf(expf(-fabsf(x)));
}
__device__ __forceinline__ uint32_t pack2(float lo, float hi) {
    __half2 h = __floats2half2_rn(lo, hi);
    return *(uint32_t*)&h;
}
__device__ __forceinline__ float red4(float v) {
    v += __shfl_xor_sync(0xffffffffu, v, 1);
    v += __shfl_xor_sync(0xffffffffu, v, 2);
    return v;
}
__device__ __forceinline__ void mma_f16(float c[4], uint32_t a0, uint32_t a1,
                                        uint32_t a2, uint32_t a3,
                                        uint32_t b0, uint32_t b1) {
    asm volatile(
        "mma.sync.aligned.m16n8k16.row.col.f32.f16.f16.f32 "
        "{%0,%1,%2,%3},{%4,%5,%6,%7},{%8,%9},{%0,%1,%2,%3};\n"
        : "+f"(c[0]), "+f"(c[1]), "+f"(c[2]), "+f"(c[3])
        : "r"(a0), "r"(a1), "r"(a2), "r"(a3), "r"(b0), "r"(b1));
}
__device__ __forceinline__ void ldsm4(uint32_t& r0, uint32_t& r1, uint32_t& r2,
                                      uint32_t& r3, uint32_t addr) {
    asm volatile("ldmatrix.sync.aligned.m8n8.x4.shared.b16 {%0,%1,%2,%3}, [%4];"
                 : "=r"(r0), "=r"(r1), "=r"(r2), "=r"(r3) : "r"(addr));
}
__device__ __forceinline__ void cp16(uint32_t dst, const void* src) {
    asm volatile("cp.async.cg.shared.global [%0], [%1], 16;" :: "r"(dst), "l"(src));
}
__device__ __forceinline__ void cp_commit() { asm volatile("cp.async.commit_group;"); }
template<int N> __device__ __forceinline__ void cp_wait() {
    asm volatile("cp.async.wait_group %0;" :: "n"(N));
}

// ---------------------------------------------------------------------------
// init + weight packing
// ---------------------------------------------------------------------------
__global__ void k_init(const float* __restrict__ h0, const float* __restrict__ s0) {
    int idx = blockIdx.x * blockDim.x + threadIdx.x;
    int stride = gridDim.x * blockDim.x;
    for (int i = idx; i < BDIM * HDIM; i += stride) {
        float v = h0[i & (HDIM - 1)];
        g_h[0][i] = v; g_h16[0][i] = __float2half_rn(v);
    }
    for (int i = idx; i < BDIM * SDIM; i += stride)
        g_s16[i] = __float2half_rn(s0[i & (SDIM - 1)]);
}

__global__ void k_prep1(const float* __restrict__ Wx, const float* __restrict__ Wh) {
    const int total = 32 * 40 * 3 * 16 * 32;
    for (int idx = blockIdx.x * blockDim.x + threadIdx.x; idx < total;
         idx += gridDim.x * blockDim.x) {
        int p = idx & 31, k2 = (idx >> 5) & 15;
        int rest = idx >> 9;
        int g = rest % 3; rest /= 3;
        int kt = rest % 40; int cb = rest / 40;
        int c = (p & 3) * 8 + (p >> 2);
        int col = g * HDIM + cb * 32 + c;
        int row = kt * 32 + 2 * k2;
        float vlo, vhi;
        if (row < 256) { vlo = Wx[(size_t)row * N3 + col]; vhi = Wx[(size_t)(row + 1) * N3 + col]; }
        else { vlo = Wh[(size_t)(row - 256) * N3 + col]; vhi = Wh[(size_t)(row - 255) * N3 + col]; }
        W1h[idx] = pack2(vlo, vhi);
    }
}
__global__ void k_prep2(const float* __restrict__ W_mu, const float* __restrict__ W_std) {
    const int total = 8 * 32 * 2 * 16 * 32;
    for (int idx = blockIdx.x * blockDim.x + threadIdx.x; idx < total;
         idx += gridDim.x * blockDim.x) {
        int p = idx & 31, k2 = (idx >> 5) & 15;
        int rest = idx >> 9;
        int g = rest & 1; rest >>= 1;
        int kt = rest & 31; int cb = rest >> 5;
        int c = (p & 3) * 8 + (p >> 2);
        const float* W = g ? W_std : W_mu;
        int row = kt * 32 + 2 * k2;
        W2h[idx] = pack2(W[(size_t)row * SDIM + cb * 32 + c],
                         W[(size_t)(row + 1) * SDIM + cb * 32 + c]);
    }
}
__global__ void k_prep3(const float* __restrict__ W_r1) {
    const int total = 16 * 40 * 16 * 32;
    for (int idx = blockIdx.x * blockDim.x + threadIdx.x; idx < total;
         idx += gridDim.x * blockDim.x) {
        int p = idx & 31, k2 = (idx >> 5) & 15;
        int rest = idx >> 9;
        int kt = rest % 40; int cb = rest / 40;
        int c = (p & 3) * 8 + (p >> 2);
        int row = kt * 32 + 2 * k2;
        W3h[idx] = pack2(W_r1[(size_t)row * RHDIM + cb * 32 + c],
                         W_r1[(size_t)(row + 1) * RHDIM + cb * 32 + c]);
    }
}

// ---------------------------------------------------------------------------
// K1 tile body: GRU gates GEMM + h update + h partial sums. col-block = by.
// ---------------------------------------------------------------------------
__device__ __forceinline__
void k1_body(int par, int t, const float* __restrict__ Wx,
             const float* __restrict__ b_gru, const int* __restrict__ acts_t, int by) {
    extern __shared__ uint32_t smem[];
    const float* __restrict__ h_in = g_h[par];
    float* __restrict__ h_out = g_h[par ^ 1];
    const __half* __restrict__ h16_in = g_h16[par];
    __half* __restrict__ h16_out = g_h16[par ^ 1];

    const int tid = threadIdx.x, lane = tid & 31, warp = tid >> 5;
    const int row0 = blockIdx.x * BM, col0 = by * BN;
    const int wr = warp * 16;
    const uint32_t smem_b = (uint32_t)__cvta_generic_to_shared(smem);

    const int c4 = tid & 3, rA = tid >> 2;
    const int wA0 = rA * AROW + c4 * 4, wA1 = (rA + 64) * AROW + c4 * 4;
    const __half* sA = g_s16 + (size_t)(row0 + rA) * SDIM + c4 * 8;
    const __half* hA = h16_in + (size_t)(row0 + rA) * HDIM + c4 * 8;
    const int bg0 = tid >> 7, bk0 = (tid >> 3) & 15, bc0 = tid & 7;
    const int wB0 = bg0 * 640 + bk0 * BROW + bc0 * 4;
    const int sB0w = bg0 * 512 + bk0 * 32 + bc0 * 4;
    const int wB1 = 2 * 640 + (tid >> 3) * BROW + (tid & 7) * 4;
    const int sB1w = 2 * 512 + (tid >> 3) * 32 + (tid & 7) * 4;
    const uint32_t* wblk = W1h + (size_t)by * (40 * 3 * 512);

#define K1_ISSUE(kt, s) do {                                                  \
    const __half* ap; int astr;                                               \
    if ((kt) < 8) { ap = sA + (kt) * 32; astr = SDIM; }                       \
    else { ap = hA + ((kt) - 8) * 32; astr = HDIM; }                          \
    cp16(smem_b + 4 * ((s) * ASTG + wA0), ap);                                \
    cp16(smem_b + 4 * ((s) * ASTG + wA1), ap + 64 * astr);                    \
    const uint32_t* wp = wblk + (size_t)(kt) * 1536;                          \
    cp16(smem_b + 4 * (ABASE + (s) * NB1 + wB0), wp + sB0w);                  \
    if (tid < 128) cp16(smem_b + 4 * (ABASE + (s) * NB1 + wB1), wp + sB1w);   \
    cp_commit(); } while (0)

    float acc[3][4][4], accNX[4][4];
#pragma unroll
    for (int g = 0; g < 3; g++)
#pragma unroll
        for (int nt = 0; nt < 4; nt++)
#pragma unroll
            for (int r = 0; r < 4; r++) acc[g][nt][r] = 0.0f;

    const int q = lane >> 2, klo = lane & 3;
    const int r1 = wr + q;
    const int bfr = klo * BROW + q * 4;
    const uint32_t aBase = smem_b + (uint32_t)(wr + (lane & 15)) * AROW * 4
                         + ((lane >> 4) * 16);

    K1_ISSUE(0, 0);
    K1_ISSUE(1, 1);
    K1_ISSUE(2, 2);

    const int KT = 40;
#pragma unroll 1
    for (int kt = 0; kt < KT; ++kt) {
        if (kt + 2 < KT) cp_wait<2>();
        else if (kt + 1 < KT) cp_wait<1>();
        else cp_wait<0>();
        __syncthreads();
        if (kt + 3 < KT) K1_ISSUE(kt + 3, (kt + 3) & 3);

        if (kt == 8) {
#pragma unroll
            for (int nt = 0; nt < 4; nt++)
#pragma unroll
                for (int r = 0; r < 4; r++) { accNX[nt][r] = acc[2][nt][r]; acc[2][nt][r] = 0.0f; }
        }
        const int sA_ = (kt & 3) * ASTG;
        const int sB_ = ABASE + (kt & 3) * NB1;
#pragma unroll
        for (int kc = 0; kc < 2; ++kc) {
            uint32_t a0, a1, a2, a3;
            ldsm4(a0, a1, a2, a3, aBase + 4 * sA_ + kc * 32);
#pragma unroll
            for (int g = 0; g < 3; g++) {
                const int bb = sB_ + g * 640 + 8 * kc * BROW + bfr;
                uint4 b0 = *(const uint4*)&smem[bb];
                uint4 b1 = *(const uint4*)&smem[bb + 4 * BROW];
                mma_f16(acc[g][0], a0, a1, a2, a3, b0.x, b1.x);
                mma_f16(acc[g][1], a0, a1, a2, a3, b0.y, b1.y);
                mma_f16(acc[g][2], a0, a1, a2, a3, b0.z, b1.z);
                mma_f16(acc[g][3], a0, a1, a2, a3, b0.w, b1.w);
            }
        }
    }
#undef K1_ISSUE

    float sumr[2] = {0.0f, 0.0f}, sqr[2] = {0.0f, 0.0f};
#pragma unroll
    for (int ri = 0; ri < 2; ri++) {
        int b = row0 + r1 + ri * 8;
        int a = acts_t[b];
        const float* wa = Wx + (size_t)(SDIM + a) * N3;
#pragma unroll
        for (int nt = 0; nt < 4; nt++) {
#pragma unroll
            for (int cj = 0; cj < 2; cj++) {
                int c = col0 + nt * 8 + 2 * klo + cj;
                int idx = ri * 2 + cj;
                float z = sigm_(acc[0][nt][idx] + wa[c] + b_gru[c]);
                float r = sigm_(acc[1][nt][idx] + wa[HDIM + c] + b_gru[HDIM + c]);
                float n = tanhf(accNX[nt][idx] + wa[2 * HDIM + c]
                                + r * acc[2][nt][idx] + b_gru[2 * HDIM + c]);
                float hp = h_in[(size_t)b * HDIM + c];
                float hv = (1.0f - z) * hp + z * n;
                h_out[(size_t)b * HDIM + c] = hv;
                h16_out[(size_t)b * HDIM + c] = __float2half_rn(hv);
                sumr[ri] += hv;
                sqr[ri] = fmaf(hv, hv, sqr[ri]);
            }
        }
    }
#pragma unroll
    for (int ri = 0; ri < 2; ri++) {
        float S = red4(sumr[ri]);
        float Q = red4(sqr[ri]);
        if (klo == 0) {
            int b = row0 + r1 + ri * 8;
            g_hS[(size_t)(t * 32 + by) * BDIM + b] = S;
            g_hQ[(size_t)(t * 32 + by) * BDIM + b] = Q;
        }
    }
}

// ---------------------------------------------------------------------------
// K3 tile body: reward hidden GEMM + fused relu.w_r2 partial dot. col-block by.
// ---------------------------------------------------------------------------
__device__ __forceinline__
void k3_body(int parn, int t, const float* __restrict__ b_r1,
             const float* __restrict__ w_r2, int by) {
    extern __shared__ uint32_t smem[];
    const __half* __restrict__ h16 = g_h16[parn];

    const int tid = threadIdx.x, lane = tid & 31, warp = tid >> 5;
    const int row0 = blockIdx.x * BM, col0 = by * BN;
    const int wr = warp * 16;
    const uint32_t smem_b = (uint32_t)__cvta_generic_to_shared(smem);

    const int c4 = tid & 3, rA = tid >> 2;
    const int wA0 = rA * AROW + c4 * 4, wA1 = (rA + 64) * AROW + c4 * 4;
    const __half* hA = h16 + (size_t)(row0 + rA) * HDIM + c4 * 8;
    const __half* sA = g_s16 + (size_t)(row0 + rA) * SDIM + c4 * 8;
    const int wB0 = (tid >> 3) * BROW + (tid & 7) * 4;
    const int sB0w = (tid >> 3) * 32 + (tid & 7) * 4;
    const uint32_t* wblk = W3h + (size_t)by * (40 * 512);

#define K3_ISSUE(kt, s) do {                                                  \
    const __half* ap; int astr;                                               \
    if ((kt) < 32) { ap = hA + (kt) * 32; astr = HDIM; }                      \
    else { ap = sA + ((kt) - 32) * 32; astr = SDIM; }                         \
    cp16(smem_b + 4 * ((s) * ASTG + wA0), ap);                                \
    cp16(smem_b + 4 * ((s) * ASTG + wA1), ap + 64 * astr);                    \
    if (tid < 128)                                                            \
        cp16(smem_b + 4 * (ABASE + (s) * NB3 + wB0), wblk + (size_t)(kt) * 512 + sB0w); \
    cp_commit(); } while (0)

    float acc[4][4];
#pragma unroll
    for (int nt = 0; nt < 4; nt++)
#pragma unroll
        for (int r = 0; r < 4; r++) acc[nt][r] = 0.0f;

    const int q = lane >> 2, klo = lane & 3;
    const int r1 = wr + q;
    const int bfr = klo * BROW + q * 4;
    const uint32_t aBase = smem_b + (uint32_t)(wr + (lane & 15)) * AROW * 4
                         + ((lane >> 4) * 16);

    K3_ISSUE(0, 0);
    K3_ISSUE(1, 1);
    K3_ISSUE(2, 2);

    const int KT = 40;
#pragma unroll 1
    for (int kt = 0; kt < KT; ++kt) {
        if (kt + 2 < KT) cp_wait<2>();
        else if (kt + 1 < KT) cp_wait<1>();
        else cp_wait<0>();
        __syncthreads();
        if (kt + 3 < KT) K3_ISSUE(kt + 3, (kt + 3) & 3);

        const int sA_ = (kt & 3) * ASTG;
        const int sB_ = ABASE + (kt & 3) * NB3;
#pragma unroll
        for (int kc = 0; kc < 2; ++kc) {
            uint32_t a0, a1, a2, a3;
            ldsm4(a0, a1, a2, a3, aBase + 4 * sA_ + kc * 32);
            const int bb = sB_ + 8 * kc * BROW + bfr;
            uint4 b0 = *(const uint4*)&smem[bb];
            uint4 b1 = *(const uint4*)&smem[bb + 4 * BROW];
            mma_f16(acc[0], a0, a1, a2, a3, b0.x, b1.x);
            mma_f16(acc[1], a0, a1, a2, a3, b0.y, b1.y);
            mma_f16(acc[2], a0, a1, a2, a3, b0.z, b1.z);
            mma_f16(acc[3], a0, a1, a2, a3, b0.w, b1.w);
        }
    }
#undef K3_ISSUE

    float dotr[2] = {0.0f, 0.0f};
#pragma unroll
    for (int ri = 0; ri < 2; ri++) {
#pragma unroll
        for (int nt = 0; nt < 4; nt++) {
#pragma unroll
            for (int cj = 0; cj < 2; cj++) {
                int c = col0 + nt * 8 + 2 * klo + cj;
                int idx = ri * 2 + cj;
                float rv = fmaxf(acc[nt][idx] + b_r1[c], 0.0f);
                dotr[ri] = fmaf(rv, w_r2[c], dotr[ri]);
            }
        }
    }
#pragma unroll
    for (int ri = 0; ri < 2; ri++) {
        float D = red4(dotr[ri]);
        if (klo == 0) {
            int b = row0 + r1 + ri * 8;
            g_rD[(size_t)(t * 16 + by) * BDIM + b] = D;
        }
    }
}

// ---------------------------------------------------------------------------
// Merged k1(t) + k3(t-1): identical inputs (h16[par], s16), disjoint outputs.
// grid (32, 48) for t>=1; (32, 32) for t=0.
// ---------------------------------------------------------------------------
__global__ __launch_bounds__(256, 2)
void k13(int par, int t, const float* __restrict__ Wx, const float* __restrict__ b_gru,
         const int* __restrict__ acts_t, const float* __restrict__ b_r1,
         const float* __restrict__ w_r2) {
    if (blockIdx.y < 32) k1_body(par, t, Wx, b_gru, acts_t, blockIdx.y);
    else k3_body(par, t - 1, b_r1, w_r2, blockIdx.y - 32);
}

__global__ __launch_bounds__(256, 2)
void k3k(int parn, int t, const float* __restrict__ b_r1, const float* __restrict__ w_r2) {
    k3_body(parn, t, b_r1, w_r2, blockIdx.y);
}

// ---------------------------------------------------------------------------
// K2: mu/std GEMM + latent sample + s partial sums. grid (32,8).
// ---------------------------------------------------------------------------
__global__ __launch_bounds__(256, 2)
void k2_latent(int parn, int t, const float* __restrict__ b_mu,
               const float* __restrict__ b_std, const float* __restrict__ noise_t) {
    extern __shared__ uint32_t smem[];
    const __half* __restrict__ h16 = g_h16[parn];

    const int tid = threadIdx.x, lane = tid & 31, warp = tid >> 5;
    const int row0 = blockIdx.x * BM, col0 = blockIdx.y * BN, by = blockIdx.y;
    const int wr = warp * 16;
    const uint32_t smem_b = (uint32_t)__cvta_generic_to_shared(smem);

    const int c4 = tid & 3, rA = tid >> 2;
    const int wA0 = rA * AROW + c4 * 4, wA1 = (rA + 64) * AROW + c4 * 4;
    const __half* hA = h16 + (size_t)(row0 + rA) * HDIM + c4 * 8;
    const int bg0 = tid >> 7, bk0 = (tid >> 3) & 15, bc0 = tid & 7;
    const int wB0 = bg0 * 640 + bk0 * BROW + bc0 * 4;
    const int sB0w = bg0 * 512 + bk0 * 32 + bc0 * 4;
    const uint32_t* wblk = W2h + (size_t)blockIdx.y * (32 * 2 * 512);

#define K2_ISSUE(kt, s) do {                                                  \
    const __half* ap = hA + (kt) * 32;                                        \
    cp16(smem_b + 4 * ((s) * ASTG + wA0), ap);                                \
    cp16(smem_b + 4 * ((s) * ASTG + wA1), ap + 64 * HDIM);                    \
    const uint32_t* wp = wblk + (size_t)(kt) * 1024;                          \
    cp16(smem_b + 4 * (ABASE + (s) * NB2 + wB0), wp + sB0w);                  \
    cp_commit(); } while (0)

    float acc[2][4][4];
#pragma unroll
    for (int g = 0; g < 2; g++)
#pragma unroll
        for (int nt = 0; nt < 4; nt++)
#pragma unroll
            for (int r = 0; r < 4; r++) acc[g][nt][r] = 0.0f;

    const int q = lane >> 2, klo = lane & 3;
    const int r1 = wr + q;
    const int bfr = klo * BROW + q * 4;
    const uint32_t aBase = smem_b + (uint32_t)(wr + (lane & 15)) * AROW * 4
                         + ((lane >> 4) * 16);

    K2_ISSUE(0, 0);
    K2_ISSUE(1, 1);
    K2_ISSUE(2, 2);

    const int KT = 32;
#pragma unroll 1
    for (int kt = 0; kt < KT; ++kt) {
        if (kt + 2 < KT) cp_wait<2>();
        else if (kt + 1 < KT) cp_wait<1>();
        else cp_wait<0>();
        __syncthreads();
        if (kt + 3 < KT) K2_ISSUE(kt + 3, (kt + 3) & 3);

        const int sA_ = (kt & 3) * ASTG;
        const int sB_ = ABASE + (kt & 3) * NB2;
#pragma unroll
        for (int kc = 0; kc < 2; ++kc) {
            uint32_t a0, a1, a2, a3;
            ldsm4(a0, a1, a2, a3, aBase + 4 * sA_ + kc * 32);
#pragma unroll
            for (int g = 0; g < 2; g++) {
                const int bb = sB_ + g * 640 + 8 * kc * BROW + bfr;
                uint4 b0 = *(const uint4*)&smem[bb];
                uint4 b1 = *(const uint4*)&smem[bb + 4 * BROW];
                mma_f16(acc[g][0], a0, a1, a2, a3, b0.x, b1.x);
                mma_f16(acc[g][1], a0, a1, a2, a3, b0.y, b1.y);
                mma_f16(acc[g][2], a0, a1, a2, a3, b0.z, b1.z);
                mma_f16(acc[g][3], a0, a1, a2, a3, b0.w, b1.w);
            }
        }
    }
#undef K2_ISSUE

    float sumr[2] = {0.0f, 0.0f}, sqr[2] = {0.0f, 0.0f};
#pragma unroll
    for (int ri = 0; ri < 2; ri++) {
        int b = row0 + r1 + ri * 8;
#pragma unroll
        for (int nt = 0; nt < 4; nt++) {
#pragma unroll
            for (int cj = 0; cj < 2; cj++) {
                int c = col0 + nt * 8 + 2 * klo + cj;
                int idx = ri * 2 + cj;
                float mu = acc[0][nt][idx] + b_mu[c];
                float sd = softplus_(acc[1][nt][idx] + b_std[c]) + 0.1f;
                float sv = mu + sd * noise_t[(size_t)b * SDIM + c];
                g_s16[(size_t)b * SDIM + c] = __float2half_rn(sv);
                sumr[ri] += sv;
                sqr[ri] = fmaf(sv, sv, sqr[ri]);
            }
        }
    }
#pragma unroll
    for (int ri = 0; ri < 2; ri++) {
        float S = red4(sumr[ri]);
        float Q = red4(sqr[ri]);
        if (klo == 0) {
            int b = row0 + r1 + ri * 8;
            g_sS[(size_t)(t * 8 + by) * BDIM + b] = S;
            g_sQ[(size_t)(t * 8 + by) * BDIM + b] = Q;
        }
    }
}

// ---------------------------------------------------------------------------
// k_efe: fold all per-step partials into g_acc (once). grid 16 x 256.
// ---------------------------------------------------------------------------
__global__ void k_efe() {
    const int b = blockIdx.x * 256 + threadIdx.x;
    float acc = 0.0f, disc = 1.0f;
#pragma unroll 1
    for (int t = 0; t < TSTEPS; t++) {
        float S = 0.0f, Q = 0.0f, D = 0.0f;
#pragma unroll
        for (int i = 0; i < 32; i++) {
            S += g_hS[(size_t)(t * 32 + i) * BDIM + b];
            Q += g_hQ[(size_t)(t * 32 + i) * BDIM + b];
        }
#pragma unroll
        for (int i = 0; i < 8; i++) {
            S += g_sS[(size_t)(t * 8 + i) * BDIM + b];
            Q += g_sQ[(size_t)(t * 8 + i) * BDIM + b];
        }
#pragma unroll
        for (int i = 0; i < 16; i++) D += g_rD[(size_t)(t * 16 + i) * BDIM + b];
        float mean = S * (1.0f / 1280.0f);
        float var = Q * (1.0f / 1280.0f) - mean * mean;
        acc += disc * (D + var);
        disc *= 0.99f;
    }
    g_acc[b] = acc;
}

__global__ void k_final(float* __restrict__ out, const float* __restrict__ b_r2,
                        float discsum) {
    const int a = blockIdx.x;
    const int tid = threadIdx.x;
    float v = g_acc[a * NSAMP + tid];
#pragma unroll
    for (int off = 16; off > 0; off >>= 1) v += __shfl_down_sync(0xffffffffu, v, off);
    __shared__ float w[8];
    if ((tid & 31) == 0) w[tid >> 5] = v;
    __syncthreads();
    if (tid < 8) {
        float x = w[tid];
#pragma unroll
        for (int off = 4; off > 0; off >>= 1) x += __shfl_down_sync(0xffu, x, off);
        if (tid == 0) out[a] = -(x * (1.0f / (float)NSAMP) + discsum * b_r2[0]);
    }
}

// ---------------------------------------------------------------------------
extern "C" void kernel_launch(void* const* d_in, const int* in_sizes, int n_in,
                              void* d_out, int out_size) {
    (void)in_sizes; (void)n_in; (void)out_size;
    const float* h0    = (const float*)d_in[0];
    const float* s0    = (const float*)d_in[1];
    const float* noise = (const float*)d_in[2];
    const float* Wx    = (const float*)d_in[3];
    const float* Wh    = (const float*)d_in[4];
    const float* b_gru = (const float*)d_in[5];
    const float* W_mu  = (const float*)d_in[6];
    const float* b_mu  = (const float*)d_in[7];
    const float* W_std = (const float*)d_in[8];
    const float* b_std = (const float*)d_in[9];
    const float* W_r1  = (const float*)d_in[10];
    const float* b_r1  = (const float*)d_in[11];
    const float* w_r2  = (const float*)d_in[12];
    const float* b_r2  = (const float*)d_in[13];
    const int*   acts  = (const int*)d_in[14];
    float* out = (float*)d_out;

    const int SM1 = (ABASE + NSTG * NB1) * 4;   // 71680 B
    const int SM2 = (ABASE + NSTG * NB2) * 4;   // 61440 B
    cudaFuncSetAttribute(k13, cudaFuncAttributeMaxDynamicSharedMemorySize, SM1);
    cudaFuncSetAttribute(k3k, cudaFuncAttributeMaxDynamicSharedMemorySize, SM1);
    cudaFuncSetAttribute(k2_latent, cudaFuncAttributeMaxDynamicSharedMemorySize, SM2);

    k_init<<<512, 256>>>(h0, s0);
    k_prep1<<<2048, 256>>>(Wx, Wh);
    k_prep2<<<256, 256>>>(W_mu, W_std);
    k_prep3<<<320, 256>>>(W_r1);

    for (int t = 0; t < TSTEPS; ++t) {
        int par = t & 1;
        int parn = par ^ 1;
        int ny = (t == 0) ? 32 : 48;
        k13<<<dim3(BDIM / BM, ny), 256, SM1>>>(par, t, Wx, b_gru,
                                               acts + (size_t)t * BDIM, b_r1, w_r2);
        k2_latent<<<dim3(BDIM / BM, SDIM / BN), 256, SM2>>>(parn, t, b_mu, b_std,
                                                            noise + (size_t)t * BDIM * SDIM);
    }
    // final step's reward GEMM (state after t=9: parn = (9&1)^1 = 0)
    k3k<<<dim3(BDIM / BM, RHDIM / BN), 256, SM1>>>(0, TSTEPS - 1, b_r1, w_r2);
    k_efe<<<16, 256>>>();

    float discsum = 0.0f, d = 1.0f;
    for (int t = 0; t < TSTEPS; ++t) { discsum += d; d *= 0.99f; }
    k_final<<<16, 256>>>(out, b_r2, discsum);
}

// round 12
// speedup vs baseline: 1.1885x; 1.0200x over previous
#include <cuda_runtime.h>
#include <cuda_fp16.h>
#include <math.h>
#include <cstdint>

// Problem constants
#define BDIM 4096
#define HDIM 1024
#define SDIM 256
#define NSAMP 256
#define TSTEPS 10
#define RHDIM 512
#define N3 3072

// Tiling: BM=128, BN=32, BK=32 (halves), 8 warps x (16 rows x 32 cols)
#define BM 128
#define BN 32
#define AROW 20              // A smem row stride in words (32 halves + pad 8)
#define ASTG 2560            // A words per stage (128*20)
#define NSTG 4               // pipeline stages
#define ABASE 10240          // NSTG * ASTG
#define BROW 40              // B smem k2-row stride in words
#define NB1 1920
#define NB2 1280
#define NB3 640
#define K2_BLOCKS 256

// Persistent scratch
__device__ float g_h[2][BDIM * HDIM];
__device__ __half g_h16[2][BDIM * HDIM];
__device__ __half g_s16[BDIM * SDIM];
__device__ float g_acc[BDIM];
__device__ int g_flag[TSTEPS];
// per-step per-CTA-column partial sums (deterministic, no atomics)
__device__ float g_hS[TSTEPS * 32 * BDIM];
__device__ float g_hQ[TSTEPS * 32 * BDIM];
__device__ float g_sS[TSTEPS * 8 * BDIM];
__device__ float g_sQ[TSTEPS * 8 * BDIM];
__device__ float g_rD[TSTEPS * 16 * BDIM];
// Pre-packed half2 weights
__device__ uint32_t W1h[32 * 40 * 3 * 16 * 32];
__device__ uint32_t W2h[8 * 32 * 2 * 16 * 32];
__device__ uint32_t W3h[16 * 40 * 16 * 32];

__device__ __forceinline__ float sigm_(float x) {
    return __fdividef(1.0f, 1.0f + __expf(-x));
}
__device__ __forceinline__ float tanh_(float x) {
    x = fminf(15.0f, fmaxf(-15.0f, x));
    float e = __expf(2.0f * x);
    return __fdividef(e - 1.0f, e + 1.0f);
}
__device__ __forceinline__ float softplus_(float x) {
    return fmaxf(x, 0.0f) + __logf(1.0f + __expf(-fabsf(x)));
}
__device__ __forceinline__ uint32_t pack2(float lo, float hi) {
    __half2 h = __floats2half2_rn(lo, hi);
    return *(uint32_t*)&h;
}
__device__ __forceinline__ float red4(float v) {
    v += __shfl_xor_sync(0xffffffffu, v, 1);
    v += __shfl_xor_sync(0xffffffffu, v, 2);
    return v;
}
__device__ __forceinline__ void mma_f16(float c[4], uint32_t a0, uint32_t a1,
                                        uint32_t a2, uint32_t a3,
                                        uint32_t b0, uint32_t b1) {
    asm volatile(
        "mma.sync.aligned.m16n8k16.row.col.f32.f16.f16.f32 "
        "{%0,%1,%2,%3},{%4,%5,%6,%7},{%8,%9},{%0,%1,%2,%3};\n"
        : "+f"(c[0]), "+f"(c[1]), "+f"(c[2]), "+f"(c[3])
        : "r"(a0), "r"(a1), "r"(a2), "r"(a3), "r"(b0), "r"(b1));
}
__device__ __forceinline__ void ldsm4(uint32_t& r0, uint32_t& r1, uint32_t& r2,
                                      uint32_t& r3, uint32_t addr) {
    asm volatile("ldmatrix.sync.aligned.m8n8.x4.shared.b16 {%0,%1,%2,%3}, [%4];"
                 : "=r"(r0), "=r"(r1), "=r"(r2), "=r"(r3) : "r"(addr));
}
__device__ __forceinline__ void cp16(uint32_t dst, const void* src) {
    asm volatile("cp.async.cg.shared.global [%0], [%1], 16;" :: "r"(dst), "l"(src));
}
__device__ __forceinline__ void cp_commit() { asm volatile("cp.async.commit_group;"); }
template<int N> __device__ __forceinline__ void cp_wait() {
    asm volatile("cp.async.wait_group %0;" :: "n"(N));
}
// Wait until step-w's k2 blocks (co-resident in this launch) have published s16.
__device__ __forceinline__ void wait_s_ready(int w) {
    if (threadIdx.x == 0) {
        volatile int* f = (volatile int*)&g_flag[w];
        while (*f < K2_BLOCKS) { }
    }
    __syncthreads();
    __threadfence();
}

// ---------------------------------------------------------------------------
// init + weight packing
// ---------------------------------------------------------------------------
__global__ void k_init(const float* __restrict__ h0, const float* __restrict__ s0) {
    int idx = blockIdx.x * blockDim.x + threadIdx.x;
    int stride = gridDim.x * blockDim.x;
    for (int i = idx; i < BDIM * HDIM; i += stride) {
        float v = h0[i & (HDIM - 1)];
        g_h[0][i] = v; g_h16[0][i] = __float2half_rn(v);
    }
    for (int i = idx; i < BDIM * SDIM; i += stride)
        g_s16[i] = __float2half_rn(s0[i & (SDIM - 1)]);
    for (int i = idx; i < TSTEPS; i += stride) g_flag[i] = 0;
}

__global__ void k_prep1(const float* __restrict__ Wx, const float* __restrict__ Wh) {
    const int total = 32 * 40 * 3 * 16 * 32;
    for (int idx = blockIdx.x * blockDim.x + threadIdx.x; idx < total;
         idx += gridDim.x * blockDim.x) {
        int p = idx & 31, k2 = (idx >> 5) & 15;
        int rest = idx >> 9;
        int g = rest % 3; rest /= 3;
        int kt = rest % 40; int cb = rest / 40;
        int c = (p & 3) * 8 + (p >> 2);
        int col = g * HDIM + cb * 32 + c;
        int row = kt * 32 + 2 * k2;
        float vlo, vhi;
        if (row < 256) { vlo = Wx[(size_t)row * N3 + col]; vhi = Wx[(size_t)(row + 1) * N3 + col]; }
        else { vlo = Wh[(size_t)(row - 256) * N3 + col]; vhi = Wh[(size_t)(row - 255) * N3 + col]; }
        W1h[idx] = pack2(vlo, vhi);
    }
}
__global__ void k_prep2(const float* __restrict__ W_mu, const float* __restrict__ W_std) {
    const int total = 8 * 32 * 2 * 16 * 32;
    for (int idx = blockIdx.x * blockDim.x + threadIdx.x; idx < total;
         idx += gridDim.x * blockDim.x) {
        int p = idx & 31, k2 = (idx >> 5) & 15;
        int rest = idx >> 9;
        int g = rest & 1; rest >>= 1;
        int kt = rest & 31; int cb = rest >> 5;
        int c = (p & 3) * 8 + (p >> 2);
        const float* W = g ? W_std : W_mu;
        int row = kt * 32 + 2 * k2;
        W2h[idx] = pack2(W[(size_t)row * SDIM + cb * 32 + c],
                         W[(size_t)(row + 1) * SDIM + cb * 32 + c]);
    }
}
__global__ void k_prep3(const float* __restrict__ W_r1) {
    const int total = 16 * 40 * 16 * 32;
    for (int idx = blockIdx.x * blockDim.x + threadIdx.x; idx < total;
         idx += gridDim.x * blockDim.x) {
        int p = idx & 31, k2 = (idx >> 5) & 15;
        int rest = idx >> 9;
        int kt = rest % 40; int cb = rest / 40;
        int c = (p & 3) * 8 + (p >> 2);
        int row = kt * 32 + 2 * k2;
        W3h[idx] = pack2(W_r1[(size_t)row * RHDIM + cb * 32 + c],
                         W_r1[(size_t)(row + 1) * RHDIM + cb * 32 + c]);
    }
}

// ---------------------------------------------------------------------------
// K1 tile body. K-order: tiles 0..31 = h-part (weight rows 256..1279),
// tiles 32..39 = s-part (weight rows 0..255) -- s is read LAST so it can be
// gated on the in-launch k2 flag. W1h layout index: h tile kt -> kt+8, s -> kt-32.
// ---------------------------------------------------------------------------
__device__ __forceinline__
void k1_body(int par, int t, const float* __restrict__ Wx,
             const float* __restrict__ b_gru, const int* __restrict__ acts_t,
             int by, int wflag) {
    extern __shared__ uint32_t smem[];
    const float* __restrict__ h_in = g_h[par];
    float* __restrict__ h_out = g_h[par ^ 1];
    const __half* __restrict__ h16_in = g_h16[par];
    __half* __restrict__ h16_out = g_h16[par ^ 1];

    const int tid = threadIdx.x, lane = tid & 31, warp = tid >> 5;
    const int row0 = blockIdx.x * BM, col0 = by * BN;
    const int wr = warp * 16;
    const uint32_t smem_b = (uint32_t)__cvta_generic_to_shared(smem);

    const int c4 = tid & 3, rA = tid >> 2;
    const int wA0 = rA * AROW + c4 * 4, wA1 = (rA + 64) * AROW + c4 * 4;
    const __half* sA = g_s16 + (size_t)(row0 + rA) * SDIM + c4 * 8;
    const __half* hA = h16_in + (size_t)(row0 + rA) * HDIM + c4 * 8;
    const int bg0 = tid >> 7, bk0 = (tid >> 3) & 15, bc0 = tid & 7;
    const int wB0 = bg0 * 640 + bk0 * BROW + bc0 * 4;
    const int sB0w = bg0 * 512 + bk0 * 32 + bc0 * 4;
    const int wB1 = 2 * 640 + (tid >> 3) * BROW + (tid & 7) * 4;
    const int sB1w = 2 * 512 + (tid >> 3) * 32 + (tid & 7) * 4;
    const uint32_t* wblk = W1h + (size_t)by * (40 * 3 * 512);

#define K1_ISSUE(kt, s) do {                                                  \
    const __half* ap; int astr; int wkt;                                      \
    if ((kt) < 32) { ap = hA + (kt) * 32; astr = HDIM; wkt = (kt) + 8; }      \
    else { ap = sA + ((kt) - 32) * 32; astr = SDIM; wkt = (kt) - 32; }        \
    cp16(smem_b + 4 * ((s) * ASTG + wA0), ap);                                \
    cp16(smem_b + 4 * ((s) * ASTG + wA1), ap + 64 * astr);                    \
    const uint32_t* wp = wblk + (size_t)wkt * 1536;                           \
    cp16(smem_b + 4 * (ABASE + (s) * NB1 + wB0), wp + sB0w);                  \
    if (tid < 128) cp16(smem_b + 4 * (ABASE + (s) * NB1 + wB1), wp + sB1w);   \
    cp_commit(); } while (0)

    float acc[3][4][4], accNH[4][4];
#pragma unroll
    for (int g = 0; g < 3; g++)
#pragma unroll
        for (int nt = 0; nt < 4; nt++)
#pragma unroll
            for (int r = 0; r < 4; r++) acc[g][nt][r] = 0.0f;

    const int q = lane >> 2, klo = lane & 3;
    const int r1 = wr + q;
    const int bfr = klo * BROW + q * 4;
    const uint32_t aBase = smem_b + (uint32_t)(wr + (lane & 15)) * AROW * 4
                         + ((lane >> 4) * 16);

    K1_ISSUE(0, 0);
    K1_ISSUE(1, 1);
    K1_ISSUE(2, 2);

    const int KT = 40;
#pragma unroll 1
    for (int kt = 0; kt < KT; ++kt) {
        if (kt + 2 < KT) cp_wait<2>();
        else if (kt + 1 < KT) cp_wait<1>();
        else cp_wait<0>();
        __syncthreads();
        if (kt == 29 && wflag >= 0) wait_s_ready(wflag);
        if (kt + 3 < KT) K1_ISSUE(kt + 3, (kt + 3) & 3);

        if (kt == 32) {
#pragma unroll
            for (int nt = 0; nt < 4; nt++)
#pragma unroll
                for (int r = 0; r < 4; r++) { accNH[nt][r] = acc[2][nt][r]; acc[2][nt][r] = 0.0f; }
        }
        const int sA_ = (kt & 3) * ASTG;
        const int sB_ = ABASE + (kt & 3) * NB1;
#pragma unroll
        for (int kc = 0; kc < 2; ++kc) {
            uint32_t a0, a1, a2, a3;
            ldsm4(a0, a1, a2, a3, aBase + 4 * sA_ + kc * 32);
#pragma unroll
            for (int g = 0; g < 3; g++) {
                const int bb = sB_ + g * 640 + 8 * kc * BROW + bfr;
                uint4 b0 = *(const uint4*)&smem[bb];
                uint4 b1 = *(const uint4*)&smem[bb + 4 * BROW];
                mma_f16(acc[g][0], a0, a1, a2, a3, b0.x, b1.x);
                mma_f16(acc[g][1], a0, a1, a2, a3, b0.y, b1.y);
                mma_f16(acc[g][2], a0, a1, a2, a3, b0.z, b1.z);
                mma_f16(acc[g][3], a0, a1, a2, a3, b0.w, b1.w);
            }
        }
    }
#undef K1_ISSUE

    float sumr[2] = {0.0f, 0.0f}, sqr[2] = {0.0f, 0.0f};
#pragma unroll
    for (int ri = 0; ri < 2; ri++) {
        int b = row0 + r1 + ri * 8;
        int a = acts_t[b];
        const float* wa = Wx + (size_t)(SDIM + a) * N3;
#pragma unroll
        for (int nt = 0; nt < 4; nt++) {
#pragma unroll
            for (int cj = 0; cj < 2; cj++) {
                int c = col0 + nt * 8 + 2 * klo + cj;
                int idx = ri * 2 + cj;
                float z = sigm_(acc[0][nt][idx] + wa[c] + b_gru[c]);
                float r = sigm_(acc[1][nt][idx] + wa[HDIM + c] + b_gru[HDIM + c]);
                float n = tanh_(acc[2][nt][idx] + wa[2 * HDIM + c]
                                + r * accNH[nt][idx] + b_gru[2 * HDIM + c]);
                float hp = h_in[(size_t)b * HDIM + c];
                float hv = (1.0f - z) * hp + z * n;
                h_out[(size_t)b * HDIM + c] = hv;
                h16_out[(size_t)b * HDIM + c] = __float2half_rn(hv);
                sumr[ri] += hv;
                sqr[ri] = fmaf(hv, hv, sqr[ri]);
            }
        }
    }
#pragma unroll
    for (int ri = 0; ri < 2; ri++) {
        float S = red4(sumr[ri]);
        float Q = red4(sqr[ri]);
        if (klo == 0) {
            int b = row0 + r1 + ri * 8;
            g_hS[(size_t)(t * 32 + by) * BDIM + b] = S;
            g_hQ[(size_t)(t * 32 + by) * BDIM + b] = Q;
        }
    }
}

// ---------------------------------------------------------------------------
// K3 tile body: s-tiles (32..39) already last; gated on wflag.
// ---------------------------------------------------------------------------
__device__ __forceinline__
void k3_body(int parn, int t, const float* __restrict__ b_r1,
             const float* __restrict__ w_r2, int by, int wflag) {
    extern __shared__ uint32_t smem[];
    const __half* __restrict__ h16 = g_h16[parn];

    const int tid = threadIdx.x, lane = tid & 31, warp = tid >> 5;
    const int row0 = blockIdx.x * BM, col0 = by * BN;
    const int wr = warp * 16;
    const uint32_t smem_b = (uint32_t)__cvta_generic_to_shared(smem);

    const int c4 = tid & 3, rA = tid >> 2;
    const int wA0 = rA * AROW + c4 * 4, wA1 = (rA + 64) * AROW + c4 * 4;
    const __half* hA = h16 + (size_t)(row0 + rA) * HDIM + c4 * 8;
    const __half* sA = g_s16 + (size_t)(row0 + rA) * SDIM + c4 * 8;
    const int wB0 = (tid >> 3) * BROW + (tid & 7) * 4;
    const int sB0w = (tid >> 3) * 32 + (tid & 7) * 4;
    const uint32_t* wblk = W3h + (size_t)by * (40 * 512);

#define K3_ISSUE(kt, s) do {                                                  \
    const __half* ap; int astr;                                               \
    if ((kt) < 32) { ap = hA + (kt) * 32; astr = HDIM; }                      \
    else { ap = sA + ((kt) - 32) * 32; astr = SDIM; }                         \
    cp16(smem_b + 4 * ((s) * ASTG + wA0), ap);                                \
    cp16(smem_b + 4 * ((s) * ASTG + wA1), ap + 64 * astr);                    \
    if (tid < 128)                                                            \
        cp16(smem_b + 4 * (ABASE + (s) * NB3 + wB0), wblk + (size_t)(kt) * 512 + sB0w); \
    cp_commit(); } while (0)

    float acc[4][4];
#pragma unroll
    for (int nt = 0; nt < 4; nt++)
#pragma unroll
        for (int r = 0; r < 4; r++) acc[nt][r] = 0.0f;

    const int q = lane >> 2, klo = lane & 3;
    const int r1 = wr + q;
    const int bfr = klo * BROW + q * 4;
    const uint32_t aBase = smem_b + (uint32_t)(wr + (lane & 15)) * AROW * 4
                         + ((lane >> 4) * 16);

    K3_ISSUE(0, 0);
    K3_ISSUE(1, 1);
    K3_ISSUE(2, 2);

    const int KT = 40;
#pragma unroll 1
    for (int kt = 0; kt < KT; ++kt) {
        if (kt + 2 < KT) cp_wait<2>();
        else if (kt + 1 < KT) cp_wait<1>();
        else cp_wait<0>();
        __syncthreads();
        if (kt == 29 && wflag >= 0) wait_s_ready(wflag);
        if (kt + 3 < KT) K3_ISSUE(kt + 3, (kt + 3) & 3);

        const int sA_ = (kt & 3) * ASTG;
        const int sB_ = ABASE + (kt & 3) * NB3;
#pragma unroll
        for (int kc = 0; kc < 2; ++kc) {
            uint32_t a0, a1, a2, a3;
            ldsm4(a0, a1, a2, a3, aBase + 4 * sA_ + kc * 32);
            const int bb = sB_ + 8 * kc * BROW + bfr;
            uint4 b0 = *(const uint4*)&smem[bb];
            uint4 b1 = *(const uint4*)&smem[bb + 4 * BROW];
            mma_f16(acc[0], a0, a1, a2, a3, b0.x, b1.x);
            mma_f16(acc[1], a0, a1, a2, a3, b0.y, b1.y);
            mma_f16(acc[2], a0, a1, a2, a3, b0.z, b1.z);
            mma_f16(acc[3], a0, a1, a2, a3, b0.w, b1.w);
        }
    }
#undef K3_ISSUE

    float dotr[2] = {0.0f, 0.0f};
#pragma unroll
    for (int ri = 0; ri < 2; ri++) {
#pragma unroll
        for (int nt = 0; nt < 4; nt++) {
#pragma unroll
            for (int cj = 0; cj < 2; cj++) {
                int c = col0 + nt * 8 + 2 * klo + cj;
                int idx = ri * 2 + cj;
                float rv = fmaxf(acc[nt][idx] + b_r1[c], 0.0f);
                dotr[ri] = fmaf(rv, w_r2[c], dotr[ri]);
            }
        }
    }
#pragma unroll
    for (int ri = 0; ri < 2; ri++) {
        float D = red4(dotr[ri]);
        if (klo == 0) {
            int b = row0 + r1 + ri * 8;
            g_rD[(size_t)(t * 16 + by) * BDIM + b] = D;
        }
    }
}

// ---------------------------------------------------------------------------
// K2 tile body: mu/std GEMM + latent sample + s partials + flag publish.
// ---------------------------------------------------------------------------
__device__ __forceinline__
void k2_body(int parn, int t, const float* __restrict__ b_mu,
             const float* __restrict__ b_std, const float* __restrict__ noise_t, int by) {
    extern __shared__ uint32_t smem[];
    const __half* __restrict__ h16 = g_h16[parn];

    const int tid = threadIdx.x, lane = tid & 31, warp = tid >> 5;
    const int row0 = blockIdx.x * BM, col0 = by * BN;
    const int wr = warp * 16;
    const uint32_t smem_b = (uint32_t)__cvta_generic_to_shared(smem);

    const int c4 = tid & 3, rA = tid >> 2;
    const int wA0 = rA * AROW + c4 * 4, wA1 = (rA + 64) * AROW + c4 * 4;
    const __half* hA = h16 + (size_t)(row0 + rA) * HDIM + c4 * 8;
    const int bg0 = tid >> 7, bk0 = (tid >> 3) & 15, bc0 = tid & 7;
    const int wB0 = bg0 * 640 + bk0 * BROW + bc0 * 4;
    const int sB0w = bg0 * 512 + bk0 * 32 + bc0 * 4;
    const uint32_t* wblk = W2h + (size_t)by * (32 * 2 * 512);

#define K2_ISSUE(kt, s) do {                                                  \
    const __half* ap = hA + (kt) * 32;                                        \
    cp16(smem_b + 4 * ((s) * ASTG + wA0), ap);                                \
    cp16(smem_b + 4 * ((s) * ASTG + wA1), ap + 64 * HDIM);                    \
    const uint32_t* wp = wblk + (size_t)(kt) * 1024;                          \
    cp16(smem_b + 4 * (ABASE + (s) * NB2 + wB0), wp + sB0w);                  \
    cp_commit(); } while (0)

    float acc[2][4][4];
#pragma unroll
    for (int g = 0; g < 2; g++)
#pragma unroll
        for (int nt = 0; nt < 4; nt++)
#pragma unroll
            for (int r = 0; r < 4; r++) acc[g][nt][r] = 0.0f;

    const int q = lane >> 2, klo = lane & 3;
    const int r1 = wr + q;
    const int bfr = klo * BROW + q * 4;
    const uint32_t aBase = smem_b + (uint32_t)(wr + (lane & 15)) * AROW * 4
                         + ((lane >> 4) * 16);

    K2_ISSUE(0, 0);
    K2_ISSUE(1, 1);
    K2_ISSUE(2, 2);

    const int KT = 32;
#pragma unroll 1
    for (int kt = 0; kt < KT; ++kt) {
        if (kt + 2 < KT) cp_wait<2>();
        else if (kt + 1 < KT) cp_wait<1>();
        else cp_wait<0>();
        __syncthreads();
        if (kt + 3 < KT) K2_ISSUE(kt + 3, (kt + 3) & 3);

        const int sA_ = (kt & 3) * ASTG;
        const int sB_ = ABASE + (kt & 3) * NB2;
#pragma unroll
        for (int kc = 0; kc < 2; ++kc) {
            uint32_t a0, a1, a2, a3;
            ldsm4(a0, a1, a2, a3, aBase + 4 * sA_ + kc * 32);
#pragma unroll
            for (int g = 0; g < 2; g++) {
                const int bb = sB_ + g * 640 + 8 * kc * BROW + bfr;
                uint4 b0 = *(const uint4*)&smem[bb];
                uint4 b1 = *(const uint4*)&smem[bb + 4 * BROW];
                mma_f16(acc[g][0], a0, a1, a2, a3, b0.x, b1.x);
                mma_f16(acc[g][1], a0, a1, a2, a3, b0.y, b1.y);
                mma_f16(acc[g][2], a0, a1, a2, a3, b0.z, b1.z);
                mma_f16(acc[g][3], a0, a1, a2, a3, b0.w, b1.w);
            }
        }
    }
#undef K2_ISSUE

    float sumr[2] = {0.0f, 0.0f}, sqr[2] = {0.0f, 0.0f};
#pragma unroll
    for (int ri = 0; ri < 2; ri++) {
        int b = row0 + r1 + ri * 8;
#pragma unroll
        for (int nt = 0; nt < 4; nt++) {
#pragma unroll
            for (int cj = 0; cj < 2; cj++) {
                int c = col0 + nt * 8 + 2 * klo + cj;
                int idx = ri * 2 + cj;
                float mu = acc[0][nt][idx] + b_mu[c];
                float sd = softplus_(acc[1][nt][idx] + b_std[c]) + 0.1f;
                float sv = mu + sd * noise_t[(size_t)b * SDIM + c];
                g_s16[(size_t)b * SDIM + c] = __float2half_rn(sv);
                sumr[ri] += sv;
                sqr[ri] = fmaf(sv, sv, sqr[ri]);
            }
        }
    }
#pragma unroll
    for (int ri = 0; ri < 2; ri++) {
        float S = red4(sumr[ri]);
        float Q = red4(sqr[ri]);
        if (klo == 0) {
            int b = row0 + r1 + ri * 8;
            g_sS[(size_t)(t * 8 + by) * BDIM + b] = S;
            g_sQ[(size_t)(t * 8 + by) * BDIM + b] = Q;
        }
    }
    // publish: s16(t) complete for this block
    __threadfence();
    __syncthreads();
    if (tid == 0) atomicAdd(&g_flag[t], 1);
}

// ---------------------------------------------------------------------------
// Step kernel, t>=1: y 0..7 = k2(t-1), y 8..39 = k1(t), y 40..55 = k3(t-1).
// k2 blocks take linear block IDs 0..255 -> dispatched first (wave 1).
// t==0: y 0..31 = k1(0), no gating (s16 = s0 from init).
// ---------------------------------------------------------------------------
__global__ __launch_bounds__(256, 2)
void kstep(int par, int t, const float* __restrict__ Wx, const float* __restrict__ b_gru,
           const int* __restrict__ acts_t, const float* __restrict__ b_r1,
           const float* __restrict__ w_r2, const float* __restrict__ b_mu,
           const float* __restrict__ b_std, const float* __restrict__ noise_prev) {
    const int y = blockIdx.y;
    if (t == 0) { k1_body(par, 0, Wx, b_gru, acts_t, y, -1); return; }
    if (y < 8) k2_body(par, t - 1, b_mu, b_std, noise_prev, y);
    else if (y < 40) k1_body(par, t, Wx, b_gru, acts_t, y - 8, t - 1);
    else k3_body(par, t - 1, b_r1, w_r2, y - 40, t - 1);
}

// Final: y 0..7 = k2(9), y 8..23 = k3(9) (gated on flag[9]).
__global__ __launch_bounds__(256, 2)
void kfin(const float* __restrict__ b_mu, const float* __restrict__ b_std,
          const float* __restrict__ noise9, const float* __restrict__ b_r1,
          const float* __restrict__ w_r2) {
    const int y = blockIdx.y;
    if (y < 8) k2_body(0, TSTEPS - 1, b_mu, b_std, noise9, y);
    else k3_body(0, TSTEPS - 1, b_r1, w_r2, y - 8, TSTEPS - 1);
}

// ---------------------------------------------------------------------------
// k_efe + k_final
// ---------------------------------------------------------------------------
__global__ void k_efe() {
    const int b = blockIdx.x * 256 + threadIdx.x;
    float acc = 0.0f, disc = 1.0f;
#pragma unroll 1
    for (int t = 0; t < TSTEPS; t++) {
        float S = 0.0f, Q = 0.0f, D = 0.0f;
#pragma unroll
        for (int i = 0; i < 32; i++) {
            S += g_hS[(size_t)(t * 32 + i) * BDIM + b];
            Q += g_hQ[(size_t)(t * 32 + i) * BDIM + b];
        }
#pragma unroll
        for (int i = 0; i < 8; i++) {
            S += g_sS[(size_t)(t * 8 + i) * BDIM + b];
            Q += g_sQ[(size_t)(t * 8 + i) * BDIM + b];
        }
#pragma unroll
        for (int i = 0; i < 16; i++) D += g_rD[(size_t)(t * 16 + i) * BDIM + b];
        float mean = S * (1.0f / 1280.0f);
        float var = Q * (1.0f / 1280.0f) - mean * mean;
        acc += disc * (D + var);
        disc *= 0.99f;
    }
    g_acc[b] = acc;
}

__global__ void k_final(float* __restrict__ out, const float* __restrict__ b_r2,
                        float discsum) {
    const int a = blockIdx.x;
    const int tid = threadIdx.x;
    float v = g_acc[a * NSAMP + tid];
#pragma unroll
    for (int off = 16; off > 0; off >>= 1) v += __shfl_down_sync(0xffffffffu, v, off);
    __shared__ float w[8];
    if ((tid & 31) == 0) w[tid >> 5] = v;
    __syncthreads();
    if (tid < 8) {
        float x = w[tid];
#pragma unroll
        for (int off = 4; off > 0; off >>= 1) x += __shfl_down_sync(0xffu, x, off);
        if (tid == 0) out[a] = -(x * (1.0f / (float)NSAMP) + discsum * b_r2[0]);
    }
}

// ---------------------------------------------------------------------------
extern "C" void kernel_launch(void* const* d_in, const int* in_sizes, int n_in,
                              void* d_out, int out_size) {
    (void)in_sizes; (void)n_in; (void)out_size;
    const float* h0    = (const float*)d_in[0];
    const float* s0    = (const float*)d_in[1];
    const float* noise = (const float*)d_in[2];
    const float* Wx    = (const float*)d_in[3];
    const float* Wh    = (const float*)d_in[4];
    const float* b_gru = (const float*)d_in[5];
    const float* W_mu  = (const float*)d_in[6];
    const float* b_mu  = (const float*)d_in[7];
    const float* W_std = (const float*)d_in[8];
    const float* b_std = (const float*)d_in[9];
    const float* W_r1  = (const float*)d_in[10];
    const float* b_r1  = (const float*)d_in[11];
    const float* w_r2  = (const float*)d_in[12];
    const float* b_r2  = (const float*)d_in[13];
    const int*   acts  = (const int*)d_in[14];
    float* out = (float*)d_out;

    const int SM1 = (ABASE + NSTG * NB1) * 4;   // 71680 B
    cudaFuncSetAttribute(kstep, cudaFuncAttributeMaxDynamicSharedMemorySize, SM1);
    cudaFuncSetAttribute(kfin, cudaFuncAttributeMaxDynamicSharedMemorySize, SM1);

    k_init<<<512, 256>>>(h0, s0);
    k_prep1<<<2048, 256>>>(Wx, Wh);
    k_prep2<<<256, 256>>>(W_mu, W_std);
    k_prep3<<<320, 256>>>(W_r1);

    for (int t = 0; t < TSTEPS; ++t) {
        int par = t & 1;
        int ny = (t == 0) ? 32 : 56;
        const float* nprev = (t == 0) ? noise : (noise + (size_t)(t - 1) * BDIM * SDIM);
        kstep<<<dim3(BDIM / BM, ny), 256, SM1>>>(par, t, Wx, b_gru,
                                                 acts + (size_t)t * BDIM, b_r1, w_r2,
                                                 b_mu, b_std, nprev);
    }
    kfin<<<dim3(BDIM / BM, 24), 256, SM1>>>(b_mu, b_std,
                                            noise + (size_t)(TSTEPS - 1) * BDIM * SDIM,
                                            b_r1, w_r2);
    k_efe<<<16, 256>>>();

    float discsum = 0.0f, d = 1.0f;
    for (int t = 0; t < TSTEPS; ++t) { discsum += d; d *= 0.99f; }
    k_final<<<16, 256>>>(out, b_r2, discsum);
}

// round 13
// speedup vs baseline: 1.1985x; 1.0084x over previous
#include <cuda_runtime.h>
#include <cuda_fp16.h>
#include <math.h>
#include <cstdint>

// Problem constants
#define BDIM 4096
#define HDIM 1024
#define SDIM 256
#define NSAMP 256
#define TSTEPS 10
#define RHDIM 512
#define N3 3072

// Tiling: BM=128, BN=32, BK=32 (halves), 8 warps x (16 rows x 32 cols)
#define BM 128
#define BN 32
#define AROW 20              // A smem row stride in words (32 halves + pad 8)
#define ASTG 2560            // A words per stage (128*20)
#define NSTG 4               // pipeline stages
#define ABASE 10240          // NSTG * ASTG
#define BROW 40              // B smem k2-row stride in words
#define NB1 1920
#define NB2 1280
#define NB3 640

// Persistent scratch
__device__ float g_h[2][BDIM * HDIM];
__device__ __half g_h16[2][BDIM * HDIM];
__device__ __half g_s16[2][BDIM * SDIM];   // double-buffered latent
__device__ float g_acc[BDIM];
// cross-step readiness flags, per (step, row-block)
__device__ int g_fh[TSTEPS][32];   // h16/h after step t ready (32 setters)
__device__ int g_fs[TSTEPS][32];   // s16 buffer (t+1)&1 ready (8 setters)
__device__ int g_fr[TSTEPS][32];   // k3(t) consumed its inputs (16 setters)
// per-step per-CTA-column partial sums (deterministic, no atomics)
__device__ float g_hS[TSTEPS * 32 * BDIM];
__device__ float g_hQ[TSTEPS * 32 * BDIM];
__device__ float g_sS[TSTEPS * 8 * BDIM];
__device__ float g_sQ[TSTEPS * 8 * BDIM];
__device__ float g_rD[TSTEPS * 16 * BDIM];
// Pre-packed half2 weights
__device__ uint32_t W1h[32 * 40 * 3 * 16 * 32];
__device__ uint32_t W2h[8 * 32 * 2 * 16 * 32];
__device__ uint32_t W3h[16 * 40 * 16 * 32];

__device__ __forceinline__ float sigm_(float x) {
    return __fdividef(1.0f, 1.0f + __expf(-x));
}
__device__ __forceinline__ float tanh_(float x) {
    x = fminf(15.0f, fmaxf(-15.0f, x));
    float e = __expf(2.0f * x);
    return __fdividef(e - 1.0f, e + 1.0f);
}
__device__ __forceinline__ float softplus_(float x) {
    return fmaxf(x, 0.0f) + __logf(1.0f + __expf(-fabsf(x)));
}
__device__ __forceinline__ uint32_t pack2(float lo, float hi) {
    __half2 h = __floats2half2_rn(lo, hi);
    return *(uint32_t*)&h;
}
__device__ __forceinline__ float red4(float v) {
    v += __shfl_xor_sync(0xffffffffu, v, 1);
    v += __shfl_xor_sync(0xffffffffu, v, 2);
    return v;
}
__device__ __forceinline__ void mma_f16(float c[4], uint32_t a0, uint32_t a1,
                                        uint32_t a2, uint32_t a3,
                                        uint32_t b0, uint32_t b1) {
    asm volatile(
        "mma.sync.aligned.m16n8k16.row.col.f32.f16.f16.f32 "
        "{%0,%1,%2,%3},{%4,%5,%6,%7},{%8,%9},{%0,%1,%2,%3};\n"
        : "+f"(c[0]), "+f"(c[1]), "+f"(c[2]), "+f"(c[3])
        : "r"(a0), "r"(a1), "r"(a2), "r"(a3), "r"(b0), "r"(b1));
}
__device__ __forceinline__ void ldsm4(uint32_t& r0, uint32_t& r1, uint32_t& r2,
                                      uint32_t& r3, uint32_t addr) {
    asm volatile("ldmatrix.sync.aligned.m8n8.x4.shared.b16 {%0,%1,%2,%3}, [%4];"
                 : "=r"(r0), "=r"(r1), "=r"(r2), "=r"(r3) : "r"(addr));
}
__device__ __forceinline__ void cp16(uint32_t dst, const void* src) {
    asm volatile("cp.async.cg.shared.global [%0], [%1], 16;" :: "r"(dst), "l"(src));
}
__device__ __forceinline__ void cp_commit() { asm volatile("cp.async.commit_group;"); }
template<int N> __device__ __forceinline__ void cp_wait() {
    asm volatile("cp.async.wait_group %0;" :: "n"(N));
}
// Block-wide wait for a flag to reach target (setters are earlier-dispatched blocks).
__device__ __forceinline__ void wait_flag(int* f, int target) {
    if (threadIdx.x == 0) {
        volatile int* vf = (volatile int*)f;
        while (*vf < target) { }
    }
    __syncthreads();
    __threadfence();
}
__device__ __forceinline__ void post_flag(int* f) {
    __threadfence();
    __syncthreads();
    if (threadIdx.x == 0) atomicAdd(f, 1);
}

// ---------------------------------------------------------------------------
// init + weight packing
// ---------------------------------------------------------------------------
__global__ void k_init(const float* __restrict__ h0, const float* __restrict__ s0) {
    int idx = blockIdx.x * blockDim.x + threadIdx.x;
    int stride = gridDim.x * blockDim.x;
    for (int i = idx; i < BDIM * HDIM; i += stride) {
        float v = h0[i & (HDIM - 1)];
        g_h[0][i] = v; g_h16[0][i] = __float2half_rn(v);
    }
    for (int i = idx; i < BDIM * SDIM; i += stride)
        g_s16[0][i] = __float2half_rn(s0[i & (SDIM - 1)]);
    for (int i = idx; i < TSTEPS * 32; i += stride) {
        ((int*)g_fh)[i] = 0; ((int*)g_fs)[i] = 0; ((int*)g_fr)[i] = 0;
    }
}

__global__ void k_prep1(const float* __restrict__ Wx, const float* __restrict__ Wh) {
    const int total = 32 * 40 * 3 * 16 * 32;
    for (int idx = blockIdx.x * blockDim.x + threadIdx.x; idx < total;
         idx += gridDim.x * blockDim.x) {
        int p = idx & 31, k2 = (idx >> 5) & 15;
        int rest = idx >> 9;
        int g = rest % 3; rest /= 3;
        int kt = rest % 40; int cb = rest / 40;
        int c = (p & 3) * 8 + (p >> 2);
        int col = g * HDIM + cb * 32 + c;
        int row = kt * 32 + 2 * k2;
        float vlo, vhi;
        if (row < 256) { vlo = Wx[(size_t)row * N3 + col]; vhi = Wx[(size_t)(row + 1) * N3 + col]; }
        else { vlo = Wh[(size_t)(row - 256) * N3 + col]; vhi = Wh[(size_t)(row - 255) * N3 + col]; }
        W1h[idx] = pack2(vlo, vhi);
    }
}
__global__ void k_prep2(const float* __restrict__ W_mu, const float* __restrict__ W_std) {
    const int total = 8 * 32 * 2 * 16 * 32;
    for (int idx = blockIdx.x * blockDim.x + threadIdx.x; idx < total;
         idx += gridDim.x * blockDim.x) {
        int p = idx & 31, k2 = (idx >> 5) & 15;
        int rest = idx >> 9;
        int g = rest & 1; rest >>= 1;
        int kt = rest & 31; int cb = rest >> 5;
        int c = (p & 3) * 8 + (p >> 2);
        const float* W = g ? W_std : W_mu;
        int row = kt * 32 + 2 * k2;
        W2h[idx] = pack2(W[(size_t)row * SDIM + cb * 32 + c],
                         W[(size_t)(row + 1) * SDIM + cb * 32 + c]);
    }
}
__global__ void k_prep3(const float* __restrict__ W_r1) {
    const int total = 16 * 40 * 16 * 32;
    for (int idx = blockIdx.x * blockDim.x + threadIdx.x; idx < total;
         idx += gridDim.x * blockDim.x) {
        int p = idx & 31, k2 = (idx >> 5) & 15;
        int rest = idx >> 9;
        int kt = rest % 40; int cb = rest / 40;
        int c = (p & 3) * 8 + (p >> 2);
        int row = kt * 32 + 2 * k2;
        W3h[idx] = pack2(W_r1[(size_t)row * RHDIM + cb * 32 + c],
                         W_r1[(size_t)(row + 1) * RHDIM + cb * 32 + c]);
    }
}

// ---------------------------------------------------------------------------
// K1 tile body, step t. Reads h16[t&1] + s16[t&1]; writes h buffers [t&1^1].
// K-order: tiles 0..31 = h-part, 32..39 = s-part (gated at kt==29).
// ---------------------------------------------------------------------------
__device__ __forceinline__
void k1_body(int t, const float* __restrict__ Wx,
             const float* __restrict__ b_gru, const int* __restrict__ acts, int by) {
    extern __shared__ uint32_t smem[];
    const int par = t & 1;
    const float* __restrict__ h_in = g_h[par];
    float* __restrict__ h_out = g_h[par ^ 1];
    const __half* __restrict__ h16_in = g_h16[par];
    __half* __restrict__ h16_out = g_h16[par ^ 1];
    const int bx = blockIdx.x;
    const int* acts_t = acts + (size_t)t * BDIM;

    if (t > 0) wait_flag(&g_fh[t - 1][bx], 32);

    const int tid = threadIdx.x, lane = tid & 31, warp = tid >> 5;
    const int row0 = bx * BM, col0 = by * BN;
    const int wr = warp * 16;
    const uint32_t smem_b = (uint32_t)__cvta_generic_to_shared(smem);

    const int c4 = tid & 3, rA = tid >> 2;
    const int wA0 = rA * AROW + c4 * 4, wA1 = (rA + 64) * AROW + c4 * 4;
    const __half* sA = g_s16[par] + (size_t)(row0 + rA) * SDIM + c4 * 8;
    const __half* hA = h16_in + (size_t)(row0 + rA) * HDIM + c4 * 8;
    const int bg0 = tid >> 7, bk0 = (tid >> 3) & 15, bc0 = tid & 7;
    const int wB0 = bg0 * 640 + bk0 * BROW + bc0 * 4;
    const int sB0w = bg0 * 512 + bk0 * 32 + bc0 * 4;
    const int wB1 = 2 * 640 + (tid >> 3) * BROW + (tid & 7) * 4;
    const int sB1w = 2 * 512 + (tid >> 3) * 32 + (tid & 7) * 4;
    const uint32_t* wblk = W1h + (size_t)by * (40 * 3 * 512);

#define K1_ISSUE(kt, s) do {                                                  \
    const __half* ap; int astr; int wkt;                                      \
    if ((kt) < 32) { ap = hA + (kt) * 32; astr = HDIM; wkt = (kt) + 8; }      \
    else { ap = sA + ((kt) - 32) * 32; astr = SDIM; wkt = (kt) - 32; }        \
    cp16(smem_b + 4 * ((s) * ASTG + wA0), ap);                                \
    cp16(smem_b + 4 * ((s) * ASTG + wA1), ap + 64 * astr);                    \
    const uint32_t* wp = wblk + (size_t)wkt * 1536;                           \
    cp16(smem_b + 4 * (ABASE + (s) * NB1 + wB0), wp + sB0w);                  \
    if (tid < 128) cp16(smem_b + 4 * (ABASE + (s) * NB1 + wB1), wp + sB1w);   \
    cp_commit(); } while (0)

    float acc[3][4][4], accNH[4][4];
#pragma unroll
    for (int g = 0; g < 3; g++)
#pragma unroll
        for (int nt = 0; nt < 4; nt++)
#pragma unroll
            for (int r = 0; r < 4; r++) acc[g][nt][r] = 0.0f;

    const int q = lane >> 2, klo = lane & 3;
    const int r1 = wr + q;
    const int bfr = klo * BROW + q * 4;
    const uint32_t aBase = smem_b + (uint32_t)(wr + (lane & 15)) * AROW * 4
                         + ((lane >> 4) * 16);

    K1_ISSUE(0, 0);
    K1_ISSUE(1, 1);
    K1_ISSUE(2, 2);

    const int KT = 40;
#pragma unroll 1
    for (int kt = 0; kt < KT; ++kt) {
        if (kt + 2 < KT) cp_wait<2>();
        else if (kt + 1 < KT) cp_wait<1>();
        else cp_wait<0>();
        __syncthreads();
        if (kt == 29 && t > 0) {
            wait_flag(&g_fs[t - 1][bx], 8);
            if (t >= 2) wait_flag(&g_fr[t - 2][bx], 16);
        }
        if (kt + 3 < KT) K1_ISSUE(kt + 3, (kt + 3) & 3);

        if (kt == 32) {
#pragma unroll
            for (int nt = 0; nt < 4; nt++)
#pragma unroll
                for (int r = 0; r < 4; r++) { accNH[nt][r] = acc[2][nt][r]; acc[2][nt][r] = 0.0f; }
        }
        const int sA_ = (kt & 3) * ASTG;
        const int sB_ = ABASE + (kt & 3) * NB1;
#pragma unroll
        for (int kc = 0; kc < 2; ++kc) {
            uint32_t a0, a1, a2, a3;
            ldsm4(a0, a1, a2, a3, aBase + 4 * sA_ + kc * 32);
#pragma unroll
            for (int g = 0; g < 3; g++) {
                const int bb = sB_ + g * 640 + 8 * kc * BROW + bfr;
                uint4 b0 = *(const uint4*)&smem[bb];
                uint4 b1 = *(const uint4*)&smem[bb + 4 * BROW];
                mma_f16(acc[g][0], a0, a1, a2, a3, b0.x, b1.x);
                mma_f16(acc[g][1], a0, a1, a2, a3, b0.y, b1.y);
                mma_f16(acc[g][2], a0, a1, a2, a3, b0.z, b1.z);
                mma_f16(acc[g][3], a0, a1, a2, a3, b0.w, b1.w);
            }
        }
    }
#undef K1_ISSUE

    float sumr[2] = {0.0f, 0.0f}, sqr[2] = {0.0f, 0.0f};
#pragma unroll
    for (int ri = 0; ri < 2; ri++) {
        int b = row0 + r1 + ri * 8;
        int a = acts_t[b];
        const float* wa = Wx + (size_t)(SDIM + a) * N3;
#pragma unroll
        for (int nt = 0; nt < 4; nt++) {
#pragma unroll
            for (int cj = 0; cj < 2; cj++) {
                int c = col0 + nt * 8 + 2 * klo + cj;
                int idx = ri * 2 + cj;
                float z = sigm_(acc[0][nt][idx] + wa[c] + b_gru[c]);
                float r = sigm_(acc[1][nt][idx] + wa[HDIM + c] + b_gru[HDIM + c]);
                float n = tanh_(acc[2][nt][idx] + wa[2 * HDIM + c]
                                + r * accNH[nt][idx] + b_gru[2 * HDIM + c]);
                float hp = h_in[(size_t)b * HDIM + c];
                float hv = (1.0f - z) * hp + z * n;
                h_out[(size_t)b * HDIM + c] = hv;
                h16_out[(size_t)b * HDIM + c] = __float2half_rn(hv);
                sumr[ri] += hv;
                sqr[ri] = fmaf(hv, hv, sqr[ri]);
            }
        }
    }
#pragma unroll
    for (int ri = 0; ri < 2; ri++) {
        float S = red4(sumr[ri]);
        float Q = red4(sqr[ri]);
        if (klo == 0) {
            int b = row0 + r1 + ri * 8;
            g_hS[(size_t)(t * 32 + by) * BDIM + b] = S;
            g_hQ[(size_t)(t * 32 + by) * BDIM + b] = Q;
        }
    }
    post_flag(&g_fh[t][bx]);
}

// ---------------------------------------------------------------------------
// K3 tile body, step j. Reads h16[(j+1)&1] + s16[(j+1)&1].
// ---------------------------------------------------------------------------
__device__ __forceinline__
void k3_body(int j, const float* __restrict__ b_r1,
             const float* __restrict__ w_r2, int by) {
    extern __shared__ uint32_t smem[];
    const int buf = (j + 1) & 1;
    const __half* __restrict__ h16 = g_h16[buf];
    const int bx = blockIdx.x;

    wait_flag(&g_fh[j][bx], 32);

    const int tid = threadIdx.x, lane = tid & 31, warp = tid >> 5;
    const int row0 = bx * BM, col0 = by * BN;
    const int wr = warp * 16;
    const uint32_t smem_b = (uint32_t)__cvta_generic_to_shared(smem);

    const int c4 = tid & 3, rA = tid >> 2;
    const int wA0 = rA * AROW + c4 * 4, wA1 = (rA + 64) * AROW + c4 * 4;
    const __half* hA = h16 + (size_t)(row0 + rA) * HDIM + c4 * 8;
    const __half* sA = g_s16[buf] + (size_t)(row0 + rA) * SDIM + c4 * 8;
    const int wB0 = (tid >> 3) * BROW + (tid & 7) * 4;
    const int sB0w = (tid >> 3) * 32 + (tid & 7) * 4;
    const uint32_t* wblk = W3h + (size_t)by * (40 * 512);

#define K3_ISSUE(kt, s) do {                                                  \
    const __half* ap; int astr;                                               \
    if ((kt) < 32) { ap = hA + (kt) * 32; astr = HDIM; }                      \
    else { ap = sA + ((kt) - 32) * 32; astr = SDIM; }                         \
    cp16(smem_b + 4 * ((s) * ASTG + wA0), ap);                                \
    cp16(smem_b + 4 * ((s) * ASTG + wA1), ap + 64 * astr);                    \
    if (tid < 128)                                                            \
        cp16(smem_b + 4 * (ABASE + (s) * NB3 + wB0), wblk + (size_t)(kt) * 512 + sB0w); \
    cp_commit(); } while (0)

    float acc[4][4];
#pragma unroll
    for (int nt = 0; nt < 4; nt++)
#pragma unroll
        for (int r = 0; r < 4; r++) acc[nt][r] = 0.0f;

    const int q = lane >> 2, klo = lane & 3;
    const int r1 = wr + q;
    const int bfr = klo * BROW + q * 4;
    const uint32_t aBase = smem_b + (uint32_t)(wr + (lane & 15)) * AROW * 4
                         + ((lane >> 4) * 16);

    K3_ISSUE(0, 0);
    K3_ISSUE(1, 1);
    K3_ISSUE(2, 2);

    const int KT = 40;
#pragma unroll 1
    for (int kt = 0; kt < KT; ++kt) {
        if (kt + 2 < KT) cp_wait<2>();
        else if (kt + 1 < KT) cp_wait<1>();
        else cp_wait<0>();
        __syncthreads();
        if (kt == 29) wait_flag(&g_fs[j][bx], 8);
        if (kt + 3 < KT) K3_ISSUE(kt + 3, (kt + 3) & 3);

        const int sA_ = (kt & 3) * ASTG;
        const int sB_ = ABASE + (kt & 3) * NB3;
#pragma unroll
        for (int kc = 0; kc < 2; ++kc) {
            uint32_t a0, a1, a2, a3;
            ldsm4(a0, a1, a2, a3, aBase + 4 * sA_ + kc * 32);
            const int bb = sB_ + 8 * kc * BROW + bfr;
            uint4 b0 = *(const uint4*)&smem[bb];
            uint4 b1 = *(const uint4*)&smem[bb + 4 * BROW];
            mma_f16(acc[0], a0, a1, a2, a3, b0.x, b1.x);
            mma_f16(acc[1], a0, a1, a2, a3, b0.y, b1.y);
            mma_f16(acc[2], a0, a1, a2, a3, b0.z, b1.z);
            mma_f16(acc[3], a0, a1, a2, a3, b0.w, b1.w);
        }
    }
#undef K3_ISSUE

    float dotr[2] = {0.0f, 0.0f};
#pragma unroll
    for (int ri = 0; ri < 2; ri++) {
#pragma unroll
        for (int nt = 0; nt < 4; nt++) {
#pragma unroll
            for (int cj = 0; cj < 2; cj++) {
                int c = col0 + nt * 8 + 2 * klo + cj;
                int idx = ri * 2 + cj;
                float rv = fmaxf(acc[nt][idx] + b_r1[c], 0.0f);
                dotr[ri] = fmaf(rv, w_r2[c], dotr[ri]);
            }
        }
    }
#pragma unroll
    for (int ri = 0; ri < 2; ri++) {
        float D = red4(dotr[ri]);
        if (klo == 0) {
            int b = row0 + r1 + ri * 8;
            g_rD[(size_t)(j * 16 + by) * BDIM + b] = D;
        }
    }
    post_flag(&g_fr[j][bx]);
}

// ---------------------------------------------------------------------------
// K2 tile body, step j. Reads h16[(j+1)&1]; writes s16[(j+1)&1].
// ---------------------------------------------------------------------------
__device__ __forceinline__
void k2_body(int j, const float* __restrict__ b_mu,
             const float* __restrict__ b_std, const float* __restrict__ noise, int by) {
    extern __shared__ uint32_t smem[];
    const int buf = (j + 1) & 1;
    const __half* __restrict__ h16 = g_h16[buf];
    const float* noise_t = noise + (size_t)j * BDIM * SDIM;
    const int bx = blockIdx.x;

    wait_flag(&g_fh[j][bx], 32);
    if (j >= 2) wait_flag(&g_fr[j - 2][bx], 16);

    const int tid = threadIdx.x, lane = tid & 31, warp = tid >> 5;
    const int row0 = bx * BM, col0 = by * BN;
    const int wr = warp * 16;
    const uint32_t smem_b = (uint32_t)__cvta_generic_to_shared(smem);

    const int c4 = tid & 3, rA = tid >> 2;
    const int wA0 = rA * AROW + c4 * 4, wA1 = (rA + 64) * AROW + c4 * 4;
    const __half* hA = h16 + (size_t)(row0 + rA) * HDIM + c4 * 8;
    const int bg0 = tid >> 7, bk0 = (tid >> 3) & 15, bc0 = tid & 7;
    const int wB0 = bg0 * 640 + bk0 * BROW + bc0 * 4;
    const int sB0w = bg0 * 512 + bk0 * 32 + bc0 * 4;
    const uint32_t* wblk = W2h + (size_t)by * (32 * 2 * 512);

#define K2_ISSUE(kt, s) do {                                                  \
    const __half* ap = hA + (kt) * 32;                                        \
    cp16(smem_b + 4 * ((s) * ASTG + wA0), ap);                                \
    cp16(smem_b + 4 * ((s) * ASTG + wA1), ap + 64 * HDIM);                    \
    const uint32_t* wp = wblk + (size_t)(kt) * 1024;                          \
    cp16(smem_b + 4 * (ABASE + (s) * NB2 + wB0), wp + sB0w);                  \
    cp_commit(); } while (0)

    float acc[2][4][4];
#pragma unroll
    for (int g = 0; g < 2; g++)
#pragma unroll
        for (int nt = 0; nt < 4; nt++)
#pragma unroll
            for (int r = 0; r < 4; r++) acc[g][nt][r] = 0.0f;

    const int q = lane >> 2, klo = lane & 3;
    const int r1 = wr + q;
    const int bfr = klo * BROW + q * 4;
    const uint32_t aBase = smem_b + (uint32_t)(wr + (lane & 15)) * AROW * 4
                         + ((lane >> 4) * 16);

    K2_ISSUE(0, 0);
    K2_ISSUE(1, 1);
    K2_ISSUE(2, 2);

    const int KT = 32;
#pragma unroll 1
    for (int kt = 0; kt < KT; ++kt) {
        if (kt + 2 < KT) cp_wait<2>();
        else if (kt + 1 < KT) cp_wait<1>();
        else cp_wait<0>();
        __syncthreads();
        if (kt + 3 < KT) K2_ISSUE(kt + 3, (kt + 3) & 3);

        const int sA_ = (kt & 3) * ASTG;
        const int sB_ = ABASE + (kt & 3) * NB2;
#pragma unroll
        for (int kc = 0; kc < 2; ++kc) {
            uint32_t a0, a1, a2, a3;
            ldsm4(a0, a1, a2, a3, aBase + 4 * sA_ + kc * 32);
#pragma unroll
            for (int g = 0; g < 2; g++) {
                const int bb = sB_ + g * 640 + 8 * kc * BROW + bfr;
                uint4 b0 = *(const uint4*)&smem[bb];
                uint4 b1 = *(const uint4*)&smem[bb + 4 * BROW];
                mma_f16(acc[g][0], a0, a1, a2, a3, b0.x, b1.x);
                mma_f16(acc[g][1], a0, a1, a2, a3, b0.y, b1.y);
                mma_f16(acc[g][2], a0, a1, a2, a3, b0.z, b1.z);
                mma_f16(acc[g][3], a0, a1, a2, a3, b0.w, b1.w);
            }
        }
    }
#undef K2_ISSUE

    __half* sOut = g_s16[(j + 1) & 1];
    float sumr[2] = {0.0f, 0.0f}, sqr[2] = {0.0f, 0.0f};
#pragma unroll
    for (int ri = 0; ri < 2; ri++) {
        int b = row0 + r1 + ri * 8;
#pragma unroll
        for (int nt = 0; nt < 4; nt++) {
#pragma unroll
            for (int cj = 0; cj < 2; cj++) {
                int c = col0 + nt * 8 + 2 * klo + cj;
                int idx = ri * 2 + cj;
                float mu = acc[0][nt][idx] + b_mu[c];
                float sd = softplus_(acc[1][nt][idx] + b_std[c]) + 0.1f;
                float sv = mu + sd * noise_t[(size_t)b * SDIM + c];
                sOut[(size_t)b * SDIM + c] = __float2half_rn(sv);
                sumr[ri] += sv;
                sqr[ri] = fmaf(sv, sv, sqr[ri]);
            }
        }
    }
#pragma unroll
    for (int ri = 0; ri < 2; ri++) {
        float S = red4(sumr[ri]);
        float Q = red4(sqr[ri]);
        if (klo == 0) {
            int b = row0 + r1 + ri * 8;
            g_sS[(size_t)(j * 8 + by) * BDIM + b] = S;
            g_sQ[(size_t)(j * 8 + by) * BDIM + b] = Q;
        }
    }
    post_flag(&g_fs[j][bx]);
}

// ---------------------------------------------------------------------------
// The whole T=10 rollout in ONE launch. grid (32, 560).
// y layout: [0,32) k1(0); per t=1..9: [32+(t-1)*56 +0,8) k2(t-1),
// [+8,40) k1(t), [+40,56) k3(t-1); tail [536,544) k2(9), [544,560) k3(9).
// ---------------------------------------------------------------------------
__global__ __launch_bounds__(256, 2)
void kall(const float* __restrict__ Wx, const float* __restrict__ b_gru,
          const int* __restrict__ acts, const float* __restrict__ b_r1,
          const float* __restrict__ w_r2, const float* __restrict__ b_mu,
          const float* __restrict__ b_std, const float* __restrict__ noise) {
    int y = blockIdx.y;
    if (y < 32) { k1_body(0, Wx, b_gru, acts, y); return; }
    y -= 32;
    if (y < 9 * 56) {
        int t = y / 56 + 1;
        int r = y % 56;
        if (r < 8) k2_body(t - 1, b_mu, b_std, noise, r);
        else if (r < 40) k1_body(t, Wx, b_gru, acts, r - 8);
        else k3_body(t - 1, b_r1, w_r2, r - 40);
    } else {
        int r = y - 9 * 56;
        if (r < 8) k2_body(TSTEPS - 1, b_mu, b_std, noise, r);
        else k3_body(TSTEPS - 1, b_r1, w_r2, r - 8);
    }
}

// ---------------------------------------------------------------------------
// k_efe + k_final
// ---------------------------------------------------------------------------
__global__ void k_efe() {
    const int b = blockIdx.x * 256 + threadIdx.x;
    float acc = 0.0f, disc = 1.0f;
#pragma unroll 1
    for (int t = 0; t < TSTEPS; t++) {
        float S = 0.0f, Q = 0.0f, D = 0.0f;
#pragma unroll
        for (int i = 0; i < 32; i++) {
            S += g_hS[(size_t)(t * 32 + i) * BDIM + b];
            Q += g_hQ[(size_t)(t * 32 + i) * BDIM + b];
        }
#pragma unroll
        for (int i = 0; i < 8; i++) {
            S += g_sS[(size_t)(t * 8 + i) * BDIM + b];
            Q += g_sQ[(size_t)(t * 8 + i) * BDIM + b];
        }
#pragma unroll
        for (int i = 0; i < 16; i++) D += g_rD[(size_t)(t * 16 + i) * BDIM + b];
        float mean = S * (1.0f / 1280.0f);
        float var = Q * (1.0f / 1280.0f) - mean * mean;
        acc += disc * (D + var);
        disc *= 0.99f;
    }
    g_acc[b] = acc;
}

__global__ void k_final(float* __restrict__ out, const float* __restrict__ b_r2,
                        float discsum) {
    const int a = blockIdx.x;
    const int tid = threadIdx.x;
    float v = g_acc[a * NSAMP + tid];
#pragma unroll
    for (int off = 16; off > 0; off >>= 1) v += __shfl_down_sync(0xffffffffu, v, off);
    __shared__ float w[8];
    if ((tid & 31) == 0) w[tid >> 5] = v;
    __syncthreads();
    if (tid < 8) {
        float x = w[tid];
#pragma unroll
        for (int off = 4; off > 0; off >>= 1) x += __shfl_down_sync(0xffu, x, off);
        if (tid == 0) out[a] = -(x * (1.0f / (float)NSAMP) + discsum * b_r2[0]);
    }
}

// ---------------------------------------------------------------------------
extern "C" void kernel_launch(void* const* d_in, const int* in_sizes, int n_in,
                              void* d_out, int out_size) {
    (void)in_sizes; (void)n_in; (void)out_size;
    const float* h0    = (const float*)d_in[0];
    const float* s0    = (const float*)d_in[1];
    const float* noise = (const float*)d_in[2];
    const float* Wx    = (const float*)d_in[3];
    const float* Wh    = (const float*)d_in[4];
    const float* b_gru = (const float*)d_in[5];
    const float* W_mu  = (const float*)d_in[6];
    const float* b_mu  = (const float*)d_in[7];
    const float* W_std = (const float*)d_in[8];
    const float* b_std = (const float*)d_in[9];
    const float* W_r1  = (const float*)d_in[10];
    const float* b_r1  = (const float*)d_in[11];
    const float* w_r2  = (const float*)d_in[12];
    const float* b_r2  = (const float*)d_in[13];
    const int*   acts  = (const int*)d_in[14];
    float* out = (float*)d_out;

    const int SM1 = (ABASE + NSTG * NB1) * 4;   // 71680 B
    cudaFuncSetAttribute(kall, cudaFuncAttributeMaxDynamicSharedMemorySize, SM1);

    k_init<<<512, 256>>>(h0, s0);
    k_prep1<<<2048, 256>>>(Wx, Wh);
    k_prep2<<<256, 256>>>(W_mu, W_std);
    k_prep3<<<320, 256>>>(W_r1);

    kall<<<dim3(32, 560), 256, SM1>>>(Wx, b_gru, acts, b_r1, w_r2, b_mu, b_std, noise);

    k_efe<<<16, 256>>>();

    float discsum = 0.0f, d = 1.0f;
    for (int t = 0; t < TSTEPS; ++t) { discsum += d; d *= 0.99f; }
    k_final<<<16, 256>>>(out, b_r2, discsum);
}

// round 14
// speedup vs baseline: 1.2337x; 1.0294x over previous
#include <cuda_runtime.h>
#include <cuda_fp16.h>
#include <math.h>
#include <cstdint>

// Problem constants
#define BDIM 4096
#define HDIM 1024
#define SDIM 256
#define NSAMP 256
#define TSTEPS 10
#define RHDIM 512
#define N3 3072

// Tiling: BM=128, BN=32, BK=32 (halves), 8 warps x (16 rows x 32 cols)
#define BM 128
#define BN 32
#define AROW 20              // A smem row stride in words (32 halves + pad 8)
#define ASTG 2560            // A words per stage (128*20)
#define NSTG 6               // pipeline stages (3 pairs)
#define ABASE 15360          // NSTG * ASTG
#define BROW 40              // B smem k2-row stride in words
#define NB1 1920
#define NB2 1280
#define NB3 640

// Persistent scratch
__device__ float g_h[2][BDIM * HDIM];
__device__ __half g_h16[2][BDIM * HDIM];
__device__ __half g_s16[2][BDIM * SDIM];   // double-buffered latent
__device__ float g_acc[BDIM];
// cross-step readiness flags, per (step, row-block)
__device__ int g_fh[TSTEPS][32];
__device__ int g_fs[TSTEPS][32];
__device__ int g_fr[TSTEPS][32];
// per-step per-CTA-column partial sums (deterministic, no atomics)
__device__ float g_hS[TSTEPS * 32 * BDIM];
__device__ float g_hQ[TSTEPS * 32 * BDIM];
__device__ float g_sS[TSTEPS * 8 * BDIM];
__device__ float g_sQ[TSTEPS * 8 * BDIM];
__device__ float g_rD[TSTEPS * 16 * BDIM];
// Pre-packed half2 weights
__device__ uint32_t W1h[32 * 40 * 3 * 16 * 32];
__device__ uint32_t W2h[8 * 32 * 2 * 16 * 32];
__device__ uint32_t W3h[16 * 40 * 16 * 32];

__device__ __forceinline__ float sigm_(float x) {
    return __fdividef(1.0f, 1.0f + __expf(-x));
}
__device__ __forceinline__ float tanh_(float x) {
    x = fminf(15.0f, fmaxf(-15.0f, x));
    float e = __expf(2.0f * x);
    return __fdividef(e - 1.0f, e + 1.0f);
}
__device__ __forceinline__ float softplus_(float x) {
    return fmaxf(x, 0.0f) + __logf(1.0f + __expf(-fabsf(x)));
}
__device__ __forceinline__ uint32_t pack2(float lo, float hi) {
    __half2 h = __floats2half2_rn(lo, hi);
    return *(uint32_t*)&h;
}
__device__ __forceinline__ float red4(float v) {
    v += __shfl_xor_sync(0xffffffffu, v, 1);
    v += __shfl_xor_sync(0xffffffffu, v, 2);
    return v;
}
__device__ __forceinline__ void mma_f16(float c[4], uint32_t a0, uint32_t a1,
                                        uint32_t a2, uint32_t a3,
                                        uint32_t b0, uint32_t b1) {
    asm volatile(
        "mma.sync.aligned.m16n8k16.row.col.f32.f16.f16.f32 "
        "{%0,%1,%2,%3},{%4,%5,%6,%7},{%8,%9},{%0,%1,%2,%3};\n"
        : "+f"(c[0]), "+f"(c[1]), "+f"(c[2]), "+f"(c[3])
        : "r"(a0), "r"(a1), "r"(a2), "r"(a3), "r"(b0), "r"(b1));
}
__device__ __forceinline__ void ldsm4(uint32_t& r0, uint32_t& r1, uint32_t& r2,
                                      uint32_t& r3, uint32_t addr) {
    asm volatile("ldmatrix.sync.aligned.m8n8.x4.shared.b16 {%0,%1,%2,%3}, [%4];"
                 : "=r"(r0), "=r"(r1), "=r"(r2), "=r"(r3) : "r"(addr));
}
__device__ __forceinline__ void cp16(uint32_t dst, const void* src) {
    asm volatile("cp.async.cg.shared.global [%0], [%1], 16;" :: "r"(dst), "l"(src));
}
__device__ __forceinline__ void cp_commit() { asm volatile("cp.async.commit_group;"); }
template<int N> __device__ __forceinline__ void cp_wait() {
    asm volatile("cp.async.wait_group %0;" :: "n"(N));
}
__device__ __forceinline__ void wait_flag(int* f, int target) {
    if (threadIdx.x == 0) {
        volatile int* vf = (volatile int*)f;
        while (*vf < target) { }
    }
    __syncthreads();
    __threadfence();
}
__device__ __forceinline__ void post_flag(int* f) {
    __threadfence();
    __syncthreads();
    if (threadIdx.x == 0) atomicAdd(f, 1);
}

// ---------------------------------------------------------------------------
// init + weight packing
// ---------------------------------------------------------------------------
__global__ void k_init(const float* __restrict__ h0, const float* __restrict__ s0) {
    int idx = blockIdx.x * blockDim.x + threadIdx.x;
    int stride = gridDim.x * blockDim.x;
    for (int i = idx; i < BDIM * HDIM; i += stride) {
        float v = h0[i & (HDIM - 1)];
        g_h[0][i] = v; g_h16[0][i] = __float2half_rn(v);
    }
    for (int i = idx; i < BDIM * SDIM; i += stride)
        g_s16[0][i] = __float2half_rn(s0[i & (SDIM - 1)]);
    for (int i = idx; i < TSTEPS * 32; i += stride) {
        ((int*)g_fh)[i] = 0; ((int*)g_fs)[i] = 0; ((int*)g_fr)[i] = 0;
    }
}

__global__ void k_prep1(const float* __restrict__ Wx, const float* __restrict__ Wh) {
    const int total = 32 * 40 * 3 * 16 * 32;
    for (int idx = blockIdx.x * blockDim.x + threadIdx.x; idx < total;
         idx += gridDim.x * blockDim.x) {
        int p = idx & 31, k2 = (idx >> 5) & 15;
        int rest = idx >> 9;
        int g = rest % 3; rest /= 3;
        int kt = rest % 40; int cb = rest / 40;
        int c = (p & 3) * 8 + (p >> 2);
        int col = g * HDIM + cb * 32 + c;
        int row = kt * 32 + 2 * k2;
        float vlo, vhi;
        if (row < 256) { vlo = Wx[(size_t)row * N3 + col]; vhi = Wx[(size_t)(row + 1) * N3 + col]; }
        else { vlo = Wh[(size_t)(row - 256) * N3 + col]; vhi = Wh[(size_t)(row - 255) * N3 + col]; }
        W1h[idx] = pack2(vlo, vhi);
    }
}
__global__ void k_prep2(const float* __restrict__ W_mu, const float* __restrict__ W_std) {
    const int total = 8 * 32 * 2 * 16 * 32;
    for (int idx = blockIdx.x * blockDim.x + threadIdx.x; idx < total;
         idx += gridDim.x * blockDim.x) {
        int p = idx & 31, k2 = (idx >> 5) & 15;
        int rest = idx >> 9;
        int g = rest & 1; rest >>= 1;
        int kt = rest & 31; int cb = rest >> 5;
        int c = (p & 3) * 8 + (p >> 2);
        const float* W = g ? W_std : W_mu;
        int row = kt * 32 + 2 * k2;
        W2h[idx] = pack2(W[(size_t)row * SDIM + cb * 32 + c],
                         W[(size_t)(row + 1) * SDIM + cb * 32 + c]);
    }
}
__global__ void k_prep3(const float* __restrict__ W_r1) {
    const int total = 16 * 40 * 16 * 32;
    for (int idx = blockIdx.x * blockDim.x + threadIdx.x; idx < total;
         idx += gridDim.x * blockDim.x) {
        int p = idx & 31, k2 = (idx >> 5) & 15;
        int rest = idx >> 9;
        int kt = rest % 40; int cb = rest / 40;
        int c = (p & 3) * 8 + (p >> 2);
        int row = kt * 32 + 2 * k2;
        W3h[idx] = pack2(W_r1[(size_t)row * RHDIM + cb * 32 + c],
                         W_r1[(size_t)(row + 1) * RHDIM + cb * 32 + c]);
    }
}

// ---------------------------------------------------------------------------
// K1 tile body, step t. K-order: tiles 0..31 h-part, 32..39 s-part.
// Pair-processed: one barrier per 2 k-tiles, 6 stages, pair prefetch dist 2.
// ---------------------------------------------------------------------------
__device__ __forceinline__
void k1_body(int t, const float* __restrict__ Wx,
             const float* __restrict__ b_gru, const int* __restrict__ acts, int by) {
    extern __shared__ uint32_t smem[];
    const int par = t & 1;
    const float* __restrict__ h_in = g_h[par];
    float* __restrict__ h_out = g_h[par ^ 1];
    const __half* __restrict__ h16_in = g_h16[par];
    __half* __restrict__ h16_out = g_h16[par ^ 1];
    const int bx = blockIdx.x;
    const int* acts_t = acts + (size_t)t * BDIM;

    if (t > 0) wait_flag(&g_fh[t - 1][bx], 32);

    const int tid = threadIdx.x, lane = tid & 31, warp = tid >> 5;
    const int row0 = bx * BM, col0 = by * BN;
    const int wr = warp * 16;
    const uint32_t smem_b = (uint32_t)__cvta_generic_to_shared(smem);

    const int c4 = tid & 3, rA = tid >> 2;
    const int wA0 = rA * AROW + c4 * 4, wA1 = (rA + 64) * AROW + c4 * 4;
    const __half* sA = g_s16[par] + (size_t)(row0 + rA) * SDIM + c4 * 8;
    const __half* hA = h16_in + (size_t)(row0 + rA) * HDIM + c4 * 8;
    const int bg0 = tid >> 7, bk0 = (tid >> 3) & 15, bc0 = tid & 7;
    const int wB0 = bg0 * 640 + bk0 * BROW + bc0 * 4;
    const int sB0w = bg0 * 512 + bk0 * 32 + bc0 * 4;
    const int wB1 = 2 * 640 + (tid >> 3) * BROW + (tid & 7) * 4;
    const int sB1w = 2 * 512 + (tid >> 3) * 32 + (tid & 7) * 4;
    const uint32_t* wblk = W1h + (size_t)by * (40 * 3 * 512);

#define K1_ISSUE(kt, s) do {                                                  \
    const __half* ap; int astr; int wkt;                                      \
    if ((kt) < 32) { ap = hA + (kt) * 32; astr = HDIM; wkt = (kt) + 8; }      \
    else { ap = sA + ((kt) - 32) * 32; astr = SDIM; wkt = (kt) - 32; }        \
    cp16(smem_b + 4 * ((s) * ASTG + wA0), ap);                                \
    cp16(smem_b + 4 * ((s) * ASTG + wA1), ap + 64 * astr);                    \
    const uint32_t* wp = wblk + (size_t)wkt * 1536;                           \
    cp16(smem_b + 4 * (ABASE + (s) * NB1 + wB0), wp + sB0w);                  \
    if (tid < 128) cp16(smem_b + 4 * (ABASE + (s) * NB1 + wB1), wp + sB1w);   \
    } while (0)

    float acc[3][4][4], accNH[4][4];
#pragma unroll
    for (int g = 0; g < 3; g++)
#pragma unroll
        for (int nt = 0; nt < 4; nt++)
#pragma unroll
            for (int r = 0; r < 4; r++) acc[g][nt][r] = 0.0f;

    const int q = lane >> 2, klo = lane & 3;
    const int r1 = wr + q;
    const int bfr = klo * BROW + q * 4;
    const uint32_t aBase = smem_b + (uint32_t)(wr + (lane & 15)) * AROW * 4
                         + ((lane >> 4) * 16);

    K1_ISSUE(0, 0); K1_ISSUE(1, 1); cp_commit();
    K1_ISSUE(2, 2); K1_ISSUE(3, 3); cp_commit();

    const int NP = 20;
    int st0 = 0, si0 = 4;
#pragma unroll 1
    for (int p = 0; p < NP; ++p) {
        if (p + 1 < NP) cp_wait<1>(); else cp_wait<0>();
        __syncthreads();
        if (p == 14 && t > 0) {
            wait_flag(&g_fs[t - 1][bx], 8);
            if (t >= 2) wait_flag(&g_fr[t - 2][bx], 16);
        }
        if (p + 2 < NP) {
            const int kti = 2 * p + 4;
            K1_ISSUE(kti, si0); K1_ISSUE(kti + 1, si0 + 1); cp_commit();
        }
        if (p == 16) {
#pragma unroll
            for (int nt = 0; nt < 4; nt++)
#pragma unroll
                for (int r = 0; r < 4; r++) { accNH[nt][r] = acc[2][nt][r]; acc[2][nt][r] = 0.0f; }
        }
#pragma unroll
        for (int half = 0; half < 2; ++half) {
            const int sA_ = (st0 + half) * ASTG;
            const int sB_ = ABASE + (st0 + half) * NB1;
#pragma unroll
            for (int kc = 0; kc < 2; ++kc) {
                uint32_t a0, a1, a2, a3;
                ldsm4(a0, a1, a2, a3, aBase + 4 * sA_ + kc * 32);
#pragma unroll
                for (int g = 0; g < 3; g++) {
                    const int bb = sB_ + g * 640 + 8 * kc * BROW + bfr;
                    uint4 b0 = *(const uint4*)&smem[bb];
                    uint4 b1 = *(const uint4*)&smem[bb + 4 * BROW];
                    mma_f16(acc[g][0], a0, a1, a2, a3, b0.x, b1.x);
                    mma_f16(acc[g][1], a0, a1, a2, a3, b0.y, b1.y);
                    mma_f16(acc[g][2], a0, a1, a2, a3, b0.z, b1.z);
                    mma_f16(acc[g][3], a0, a1, a2, a3, b0.w, b1.w);
                }
            }
        }
        st0 += 2; if (st0 == NSTG) st0 = 0;
        si0 += 2; if (si0 == NSTG) si0 = 0;
    }
#undef K1_ISSUE

    float sumr[2] = {0.0f, 0.0f}, sqr[2] = {0.0f, 0.0f};
#pragma unroll
    for (int ri = 0; ri < 2; ri++) {
        int b = row0 + r1 + ri * 8;
        int a = acts_t[b];
        const float* wa = Wx + (size_t)(SDIM + a) * N3;
#pragma unroll
        for (int nt = 0; nt < 4; nt++) {
#pragma unroll
            for (int cj = 0; cj < 2; cj++) {
                int c = col0 + nt * 8 + 2 * klo + cj;
                int idx = ri * 2 + cj;
                float z = sigm_(acc[0][nt][idx] + wa[c] + b_gru[c]);
                float r = sigm_(acc[1][nt][idx] + wa[HDIM + c] + b_gru[HDIM + c]);
                float n = tanh_(acc[2][nt][idx] + wa[2 * HDIM + c]
                                + r * accNH[nt][idx] + b_gru[2 * HDIM + c]);
                float hp = h_in[(size_t)b * HDIM + c];
                float hv = (1.0f - z) * hp + z * n;
                h_out[(size_t)b * HDIM + c] = hv;
                h16_out[(size_t)b * HDIM + c] = __float2half_rn(hv);
                sumr[ri] += hv;
                sqr[ri] = fmaf(hv, hv, sqr[ri]);
            }
        }
    }
#pragma unroll
    for (int ri = 0; ri < 2; ri++) {
        float S = red4(sumr[ri]);
        float Q = red4(sqr[ri]);
        if (klo == 0) {
            int b = row0 + r1 + ri * 8;
            g_hS[(size_t)(t * 32 + by) * BDIM + b] = S;
            g_hQ[(size_t)(t * 32 + by) * BDIM + b] = Q;
        }
    }
    post_flag(&g_fh[t][bx]);
}

// ---------------------------------------------------------------------------
// K3 tile body, step j. Pair-processed; s-tiles last, gated at pair-16 issue.
// ---------------------------------------------------------------------------
__device__ __forceinline__
void k3_body(int j, const float* __restrict__ b_r1,
             const float* __restrict__ w_r2, int by) {
    extern __shared__ uint32_t smem[];
    const int buf = (j + 1) & 1;
    const __half* __restrict__ h16 = g_h16[buf];
    const int bx = blockIdx.x;

    wait_flag(&g_fh[j][bx], 32);

    const int tid = threadIdx.x, lane = tid & 31, warp = tid >> 5;
    const int row0 = bx * BM, col0 = by * BN;
    const int wr = warp * 16;
    const uint32_t smem_b = (uint32_t)__cvta_generic_to_shared(smem);

    const int c4 = tid & 3, rA = tid >> 2;
    const int wA0 = rA * AROW + c4 * 4, wA1 = (rA + 64) * AROW + c4 * 4;
    const __half* hA = h16 + (size_t)(row0 + rA) * HDIM + c4 * 8;
    const __half* sA = g_s16[buf] + (size_t)(row0 + rA) * SDIM + c4 * 8;
    const int wB0 = (tid >> 3) * BROW + (tid & 7) * 4;
    const int sB0w = (tid >> 3) * 32 + (tid & 7) * 4;
    const uint32_t* wblk = W3h + (size_t)by * (40 * 512);

#define K3_ISSUE(kt, s) do {                                                  \
    const __half* ap; int astr;                                               \
    if ((kt) < 32) { ap = hA + (kt) * 32; astr = HDIM; }                      \
    else { ap = sA + ((kt) - 32) * 32; astr = SDIM; }                         \
    cp16(smem_b + 4 * ((s) * ASTG + wA0), ap);                                \
    cp16(smem_b + 4 * ((s) * ASTG + wA1), ap + 64 * astr);                    \
    if (tid < 128)                                                            \
        cp16(smem_b + 4 * (ABASE + (s) * NB3 + wB0), wblk + (size_t)(kt) * 512 + sB0w); \
    } while (0)

    float acc[4][4];
#pragma unroll
    for (int nt = 0; nt < 4; nt++)
#pragma unroll
        for (int r = 0; r < 4; r++) acc[nt][r] = 0.0f;

    const int q = lane >> 2, klo = lane & 3;
    const int r1 = wr + q;
    const int bfr = klo * BROW + q * 4;
    const uint32_t aBase = smem_b + (uint32_t)(wr + (lane & 15)) * AROW * 4
                         + ((lane >> 4) * 16);

    K3_ISSUE(0, 0); K3_ISSUE(1, 1); cp_commit();
    K3_ISSUE(2, 2); K3_ISSUE(3, 3); cp_commit();

    const int NP = 20;
    int st0 = 0, si0 = 4;
#pragma unroll 1
    for (int p = 0; p < NP; ++p) {
        if (p + 1 < NP) cp_wait<1>(); else cp_wait<0>();
        __syncthreads();
        if (p == 14) wait_flag(&g_fs[j][bx], 8);
        if (p + 2 < NP) {
            const int kti = 2 * p + 4;
            K3_ISSUE(kti, si0); K3_ISSUE(kti + 1, si0 + 1); cp_commit();
        }
#pragma unroll
        for (int half = 0; half < 2; ++half) {
            const int sA_ = (st0 + half) * ASTG;
            const int sB_ = ABASE + (st0 + half) * NB3;
#pragma unroll
            for (int kc = 0; kc < 2; ++kc) {
                uint32_t a0, a1, a2, a3;
                ldsm4(a0, a1, a2, a3, aBase + 4 * sA_ + kc * 32);
                const int bb = sB_ + 8 * kc * BROW + bfr;
                uint4 b0 = *(const uint4*)&smem[bb];
                uint4 b1 = *(const uint4*)&smem[bb + 4 * BROW];
                mma_f16(acc[0], a0, a1, a2, a3, b0.x, b1.x);
                mma_f16(acc[1], a0, a1, a2, a3, b0.y, b1.y);
                mma_f16(acc[2], a0, a1, a2, a3, b0.z, b1.z);
                mma_f16(acc[3], a0, a1, a2, a3, b0.w, b1.w);
            }
        }
        st0 += 2; if (st0 == NSTG) st0 = 0;
        si0 += 2; if (si0 == NSTG) si0 = 0;
    }
#undef K3_ISSUE

    float dotr[2] = {0.0f, 0.0f};
#pragma unroll
    for (int ri = 0; ri < 2; ri++) {
#pragma unroll
        for (int nt = 0; nt < 4; nt++) {
#pragma unroll
            for (int cj = 0; cj < 2; cj++) {
                int c = col0 + nt * 8 + 2 * klo + cj;
                int idx = ri * 2 + cj;
                float rv = fmaxf(acc[nt][idx] + b_r1[c], 0.0f);
                dotr[ri] = fmaf(rv, w_r2[c], dotr[ri]);
            }
        }
    }
#pragma unroll
    for (int ri = 0; ri < 2; ri++) {
        float D = red4(dotr[ri]);
        if (klo == 0) {
            int b = row0 + r1 + ri * 8;
            g_rD[(size_t)(j * 16 + by) * BDIM + b] = D;
        }
    }
    post_flag(&g_fr[j][bx]);
}

// ---------------------------------------------------------------------------
// K2 tile body, step j. Pair-processed. Reads h16[(j+1)&1]; writes s16[(j+1)&1].
// ---------------------------------------------------------------------------
__device__ __forceinline__
void k2_body(int j, const float* __restrict__ b_mu,
             const float* __restrict__ b_std, const float* __restrict__ noise, int by) {
    extern __shared__ uint32_t smem[];
    const int buf = (j + 1) & 1;
    const __half* __restrict__ h16 = g_h16[buf];
    const float* noise_t = noise + (size_t)j * BDIM * SDIM;
    const int bx = blockIdx.x;

    wait_flag(&g_fh[j][bx], 32);
    if (j >= 2) wait_flag(&g_fr[j - 2][bx], 16);

    const int tid = threadIdx.x, lane = tid & 31, warp = tid >> 5;
    const int row0 = bx * BM, col0 = by * BN;
    const int wr = warp * 16;
    const uint32_t smem_b = (uint32_t)__cvta_generic_to_shared(smem);

    const int c4 = tid & 3, rA = tid >> 2;
    const int wA0 = rA * AROW + c4 * 4, wA1 = (rA + 64) * AROW + c4 * 4;
    const __half* hA = h16 + (size_t)(row0 + rA) * HDIM + c4 * 8;
    const int bg0 = tid >> 7, bk0 = (tid >> 3) & 15, bc0 = tid & 7;
    const int wB0 = bg0 * 640 + bk0 * BROW + bc0 * 4;
    const int sB0w = bg0 * 512 + bk0 * 32 + bc0 * 4;
    const uint32_t* wblk = W2h + (size_t)by * (32 * 2 * 512);

#define K2_ISSUE(kt, s) do {                                                  \
    const __half* ap = hA + (kt) * 32;                                        \
    cp16(smem_b + 4 * ((s) * ASTG + wA0), ap);                                \
    cp16(smem_b + 4 * ((s) * ASTG + wA1), ap + 64 * HDIM);                    \
    const uint32_t* wp = wblk + (size_t)(kt) * 1024;                          \
    cp16(smem_b + 4 * (ABASE + (s) * NB2 + wB0), wp + sB0w);                  \
    } while (0)

    float acc[2][4][4];
#pragma unroll
    for (int g = 0; g < 2; g++)
#pragma unroll
        for (int nt = 0; nt < 4; nt++)
#pragma unroll
            for (int r = 0; r < 4; r++) acc[g][nt][r] = 0.0f;

    const int q = lane >> 2, klo = lane & 3;
    const int r1 = wr + q;
    const int bfr = klo * BROW + q * 4;
    const uint32_t aBase = smem_b + (uint32_t)(wr + (lane & 15)) * AROW * 4
                         + ((lane >> 4) * 16);

    K2_ISSUE(0, 0); K2_ISSUE(1, 1); cp_commit();
    K2_ISSUE(2, 2); K2_ISSUE(3, 3); cp_commit();

    const int NP = 16;
    int st0 = 0, si0 = 4;
#pragma unroll 1
    for (int p = 0; p < NP; ++p) {
        if (p + 1 < NP) cp_wait<1>(); else cp_wait<0>();
        __syncthreads();
        if (p + 2 < NP) {
            const int kti = 2 * p + 4;
            K2_ISSUE(kti, si0); K2_ISSUE(kti + 1, si0 + 1); cp_commit();
        }
#pragma unroll
        for (int half = 0; half < 2; ++half) {
            const int sA_ = (st0 + half) * ASTG;
            const int sB_ = ABASE + (st0 + half) * NB2;
#pragma unroll
            for (int kc = 0; kc < 2; ++kc) {
                uint32_t a0, a1, a2, a3;
                ldsm4(a0, a1, a2, a3, aBase + 4 * sA_ + kc * 32);
#pragma unroll
                for (int g = 0; g < 2; g++) {
                    const int bb = sB_ + g * 640 + 8 * kc * BROW + bfr;
                    uint4 b0 = *(const uint4*)&smem[bb];
                    uint4 b1 = *(const uint4*)&smem[bb + 4 * BROW];
                    mma_f16(acc[g][0], a0, a1, a2, a3, b0.x, b1.x);
                    mma_f16(acc[g][1], a0, a1, a2, a3, b0.y, b1.y);
                    mma_f16(acc[g][2], a0, a1, a2, a3, b0.z, b1.z);
                    mma_f16(acc[g][3], a0, a1, a2, a3, b0.w, b1.w);
                }
            }
        }
        st0 += 2; if (st0 == NSTG) st0 = 0;
        si0 += 2; if (si0 == NSTG) si0 = 0;
    }
#undef K2_ISSUE

    __half* sOut = g_s16[(j + 1) & 1];
    float sumr[2] = {0.0f, 0.0f}, sqr[2] = {0.0f, 0.0f};
#pragma unroll
    for (int ri = 0; ri < 2; ri++) {
        int b = row0 + r1 + ri * 8;
#pragma unroll
        for (int nt = 0; nt < 4; nt++) {
#pragma unroll
            for (int cj = 0; cj < 2; cj++) {
                int c = col0 + nt * 8 + 2 * klo + cj;
                int idx = ri * 2 + cj;
                float mu = acc[0][nt][idx] + b_mu[c];
                float sd = softplus_(acc[1][nt][idx] + b_std[c]) + 0.1f;
                float sv = mu + sd * noise_t[(size_t)b * SDIM + c];
                sOut[(size_t)b * SDIM + c] = __float2half_rn(sv);
                sumr[ri] += sv;
                sqr[ri] = fmaf(sv, sv, sqr[ri]);
            }
        }
    }
#pragma unroll
    for (int ri = 0; ri < 2; ri++) {
        float S = red4(sumr[ri]);
        float Q = red4(sqr[ri]);
        if (klo == 0) {
            int b = row0 + r1 + ri * 8;
            g_sS[(size_t)(j * 8 + by) * BDIM + b] = S;
            g_sQ[(size_t)(j * 8 + by) * BDIM + b] = Q;
        }
    }
    post_flag(&g_fs[j][bx]);
}

// ---------------------------------------------------------------------------
// The whole T=10 rollout in ONE launch. grid (32, 560).
// ---------------------------------------------------------------------------
__global__ __launch_bounds__(256, 2)
void kall(const float* __restrict__ Wx, const float* __restrict__ b_gru,
          const int* __restrict__ acts, const float* __restrict__ b_r1,
          const float* __restrict__ w_r2, const float* __restrict__ b_mu,
          const float* __restrict__ b_std, const float* __restrict__ noise) {
    int y = blockIdx.y;
    if (y < 32) { k1_body(0, Wx, b_gru, acts, y); return; }
    y -= 32;
    if (y < 9 * 56) {
        int t = y / 56 + 1;
        int r = y % 56;
        if (r < 8) k2_body(t - 1, b_mu, b_std, noise, r);
        else if (r < 40) k1_body(t, Wx, b_gru, acts, r - 8);
        else k3_body(t - 1, b_r1, w_r2, r - 40);
    } else {
        int r = y - 9 * 56;
        if (r < 8) k2_body(TSTEPS - 1, b_mu, b_std, noise, r);
        else k3_body(TSTEPS - 1, b_r1, w_r2, r - 8);
    }
}

// ---------------------------------------------------------------------------
// k_efe + k_final
// ---------------------------------------------------------------------------
__global__ void k_efe() {
    const int b = blockIdx.x * 256 + threadIdx.x;
    float acc = 0.0f, disc = 1.0f;
#pragma unroll 1
    for (int t = 0; t < TSTEPS; t++) {
        float S = 0.0f, Q = 0.0f, D = 0.0f;
#pragma unroll
        for (int i = 0; i < 32; i++) {
            S += g_hS[(size_t)(t * 32 + i) * BDIM + b];
            Q += g_hQ[(size_t)(t * 32 + i) * BDIM + b];
        }
#pragma unroll
        for (int i = 0; i < 8; i++) {
            S += g_sS[(size_t)(t * 8 + i) * BDIM + b];
            Q += g_sQ[(size_t)(t * 8 + i) * BDIM + b];
        }
#pragma unroll
        for (int i = 0; i < 16; i++) D += g_rD[(size_t)(t * 16 + i) * BDIM + b];
        float mean = S * (1.0f / 1280.0f);
        float var = Q * (1.0f / 1280.0f) - mean * mean;
        acc += disc * (D + var);
        disc *= 0.99f;
    }
    g_acc[b] = acc;
}

__global__ void k_final(float* __restrict__ out, const float* __restrict__ b_r2,
                        float discsum) {
    const int a = blockIdx.x;
    const int tid = threadIdx.x;
    float v = g_acc[a * NSAMP + tid];
#pragma unroll
    for (int off = 16; off > 0; off >>= 1) v += __shfl_down_sync(0xffffffffu, v, off);
    __shared__ float w[8];
    if ((tid & 31) == 0) w[tid >> 5] = v;
    __syncthreads();
    if (tid < 8) {
        float x = w[tid];
#pragma unroll
        for (int off = 4; off > 0; off >>= 1) x += __shfl_down_sync(0xffu, x, off);
        if (tid == 0) out[a] = -(x * (1.0f / (float)NSAMP) + discsum * b_r2[0]);
    }
}

// ---------------------------------------------------------------------------
extern "C" void kernel_launch(void* const* d_in, const int* in_sizes, int n_in,
                              void* d_out, int out_size) {
    (void)in_sizes; (void)n_in; (void)out_size;
    const float* h0    = (const float*)d_in[0];
    const float* s0    = (const float*)d_in[1];
    const float* noise = (const float*)d_in[2];
    const float* Wx    = (const float*)d_in[3];
    const float* Wh    = (const float*)d_in[4];
    const float* b_gru = (const float*)d_in[5];
    const float* W_mu  = (const float*)d_in[6];
    const float* b_mu  = (const float*)d_in[7];
    const float* W_std = (const float*)d_in[8];
    const float* b_std = (const float*)d_in[9];
    const float* W_r1  = (const float*)d_in[10];
    const float* b_r1  = (const float*)d_in[11];
    const float* w_r2  = (const float*)d_in[12];
    const float* b_r2  = (const float*)d_in[13];
    const int*   acts  = (const int*)d_in[14];
    float* out = (float*)d_out;

    const int SM1 = (ABASE + NSTG * NB1) * 4;   // 107520 B
    cudaFuncSetAttribute(kall, cudaFuncAttributeMaxDynamicSharedMemorySize, SM1);

    k_init<<<512, 256>>>(h0, s0);
    k_prep1<<<2048, 256>>>(Wx, Wh);
    k_prep2<<<256, 256>>>(W_mu, W_std);
    k_prep3<<<320, 256>>>(W_r1);

    kall<<<dim3(32, 560), 256, SM1>>>(Wx, b_gru, acts, b_r1, w_r2, b_mu, b_std, noise);

    k_efe<<<16, 256>>>();

    float discsum = 0.0f, d = 1.0f;
    for (int t = 0; t < TSTEPS; ++t) { discsum += d; d *= 0.99f; }
    k_final<<<16, 256>>>(out, b_r2, discsum);
}